// round 1
// baseline (speedup 1.0000x reference)
#include <cuda_runtime.h>
#include <cuda_bf16.h>
#include <cstdint>
#include <cstdio>

// Problem constants
#define BB   64
#define SRC  2048
#define ENCD 1024
#define UU   1024
#define EE   512
#define VV   32000
#define IN0  (ENCD + EE)        // 1536
#define MROWS (BB * SRC)        // 131072

// ---------------- scratch (device globals; no allocation allowed) -----------
__device__ float g_h[BB * UU];              // state@Wh + bh
__device__ float g_spart[8 * MROWS];        // per-jtile partial scores (16.8MB)
__device__ float g_w[BB * SRC];             // softmax weights
__device__ float g_ctx[BB * ENCD];          // attention context
__device__ float g_xin[BB * IN0];           // concat(ctx, emb)
__device__ float g_xg[BB * 3 * UU];         // GRU gate pre-activations
__device__ float g_y[BB * 2 * UU];          // concat(h1f, h1b)

// ---------------- helpers ----------------------------------------------------
__device__ __forceinline__ unsigned f2tf32(float f) {
    unsigned u;
    asm("cvt.rna.tf32.f32 %0, %1;" : "=r"(u) : "f"(f));
    return u;
}
__device__ __forceinline__ uint4 cvt4(float4 v) {
    uint4 u;
    u.x = f2tf32(v.x); u.y = f2tf32(v.y); u.z = f2tf32(v.z); u.w = f2tf32(v.w);
    return u;
}
__device__ __forceinline__ float htanh(float x) {
    float r;
    asm("tanh.approx.f32 %0, %1;" : "=f"(r) : "f"(x));
    return r;
}

#define MMA_TF32(c, a, b)                                                        \
    asm volatile(                                                                \
        "mma.sync.aligned.m16n8k8.row.col.f32.tf32.tf32.f32 "                    \
        "{%0,%1,%2,%3},{%4,%5,%6,%7},{%8,%9},{%0,%1,%2,%3};\n"                   \
        : "+f"((c)[0]), "+f"((c)[1]), "+f"((c)[2]), "+f"((c)[3])                 \
        : "r"((a)[0]), "r"((a)[1]), "r"((a)[2]), "r"((a)[3]),                    \
          "r"((b)[0]), "r"((b)[1]))

// ---------------- k_h : h = state @ att_Wh + bh  (64 x 1024) ----------------
__global__ void k_h(const float* __restrict__ state, const float* __restrict__ Wh,
                    const float* __restrict__ bh) {
    int b = blockIdx.x;
    __shared__ float ss[ENCD];
    for (int i = threadIdx.x; i < UU; i += 256) ss[i] = state[b * UU + i];
    __syncthreads();
    float acc[4] = {0.f, 0.f, 0.f, 0.f};
#pragma unroll 4
    for (int k = 0; k < UU; k++) {
        float sv = ss[k];
        const float* wr = Wh + (size_t)k * UU + threadIdx.x;
        acc[0] += sv * wr[0];
        acc[1] += sv * wr[256];
        acc[2] += sv * wr[512];
        acc[3] += sv * wr[768];
    }
#pragma unroll
    for (int jj = 0; jj < 4; jj++) {
        int j = threadIdx.x + jj * 256;
        g_h[b * UU + j] = acc[jj] + bh[j];
    }
}

// ---------------- k_score : fused enc@Wc + tanh(.+h+bc)*Ws reduction --------
// grid: (8 j-tiles, 1024 row-blocks), block: 256 threads (8 warps, warp 64x32)
__global__ __launch_bounds__(256, 2) void k_score(const float* __restrict__ enc,
                                                  const float* __restrict__ Wc,
                                                  const float* __restrict__ bc,
                                                  const float* __restrict__ Ws) {
    __shared__ __align__(16) unsigned sA[128 * 36];
    __shared__ __align__(16) unsigned sB[32 * 132];
    __shared__ float srow[128];

    const int tid = threadIdx.x;
    const int jb = blockIdx.x;          // 0..7
    const int R0 = blockIdx.y * 128;    // row block start
    if (tid < 128) srow[tid] = 0.f;

    const int wid = tid >> 5, lane = tid & 31;
    const int wm = wid & 1, wn = wid >> 1;
    const int g = lane >> 2, tg = lane & 3;
    const int jcol0 = jb * 128;

    float c[4][4][4];
#pragma unroll
    for (int a = 0; a < 4; a++)
#pragma unroll
        for (int b2 = 0; b2 < 4; b2++)
#pragma unroll
            for (int d = 0; d < 4; d++) c[a][b2][d] = 0.f;

    for (int k0 = 0; k0 < ENCD; k0 += 32) {
#pragma unroll
        for (int i = 0; i < 4; i++) {  // A: 128x32
            int idx = tid + i * 256;
            int row = idx >> 3, c4 = idx & 7;
            float4 v = *reinterpret_cast<const float4*>(
                enc + (size_t)(R0 + row) * ENCD + k0 + c4 * 4);
            *reinterpret_cast<uint4*>(&sA[row * 36 + c4 * 4]) = cvt4(v);
        }
#pragma unroll
        for (int i = 0; i < 4; i++) {  // B: 32x128
            int idx = tid + i * 256;
            int rb = idx >> 5, c4 = idx & 31;
            float4 v = *reinterpret_cast<const float4*>(
                Wc + (size_t)(k0 + rb) * ENCD + jcol0 + c4 * 4);
            *reinterpret_cast<uint4*>(&sB[rb * 132 + c4 * 4]) = cvt4(v);
        }
        __syncthreads();
#pragma unroll
        for (int ks = 0; ks < 4; ks++) {
            const int kb = ks * 8;
            unsigned af[4][4], bf[4][2];
#pragma unroll
            for (int mt = 0; mt < 4; mt++) {
                int r = wm * 64 + mt * 16 + g;
                af[mt][0] = sA[r * 36 + kb + tg];
                af[mt][1] = sA[(r + 8) * 36 + kb + tg];
                af[mt][2] = sA[r * 36 + kb + tg + 4];
                af[mt][3] = sA[(r + 8) * 36 + kb + tg + 4];
            }
#pragma unroll
            for (int nt = 0; nt < 4; nt++) {
                int col = wn * 32 + nt * 8 + g;
                bf[nt][0] = sB[(kb + tg) * 132 + col];
                bf[nt][1] = sB[(kb + tg + 4) * 132 + col];
            }
#pragma unroll
            for (int mt = 0; mt < 4; mt++)
#pragma unroll
                for (int nt = 0; nt < 4; nt++) MMA_TF32(c[mt][nt], af[mt], bf[nt]);
        }
        __syncthreads();
    }

    // epilogue: s_partial[row] = sum_j tanh(c + h[b][j] + bc[j]) * Ws[j]
    const int bidx = R0 >> 11;  // 2048 rows per batch element; 128 | 2048
    float hb[4][2], wsv[4][2];
#pragma unroll
    for (int nt = 0; nt < 4; nt++)
#pragma unroll
        for (int cc = 0; cc < 2; cc++) {
            int j = jcol0 + wn * 32 + nt * 8 + tg * 2 + cc;
            hb[nt][cc] = g_h[bidx * UU + j] + bc[j];
            wsv[nt][cc] = Ws[j];
        }
#pragma unroll
    for (int mt = 0; mt < 4; mt++) {
        float rs0 = 0.f, rs1 = 0.f;
#pragma unroll
        for (int nt = 0; nt < 4; nt++)
#pragma unroll
            for (int cc = 0; cc < 2; cc++) {
                rs0 += htanh(c[mt][nt][cc] + hb[nt][cc]) * wsv[nt][cc];
                rs1 += htanh(c[mt][nt][2 + cc] + hb[nt][cc]) * wsv[nt][cc];
            }
        rs0 += __shfl_xor_sync(0xffffffffu, rs0, 1);
        rs0 += __shfl_xor_sync(0xffffffffu, rs0, 2);
        rs1 += __shfl_xor_sync(0xffffffffu, rs1, 1);
        rs1 += __shfl_xor_sync(0xffffffffu, rs1, 2);
        if (tg == 0) {
            atomicAdd(&srow[wm * 64 + mt * 16 + g], rs0);
            atomicAdd(&srow[wm * 64 + mt * 16 + 8 + g], rs1);
        }
    }
    __syncthreads();
    if (tid < 128) g_spart[jb * MROWS + R0 + tid] = srow[tid];
}

// ---------------- k_softmax : per-b softmax over 2048 scores ----------------
__global__ void k_softmax(const float* __restrict__ bs) {
    __shared__ float sv[SRC];
    __shared__ float red[256];
    int b = blockIdx.x, tid = threadIdx.x;
    float bsv = bs[0];
    float lmax = -1e30f;
    for (int t = tid; t < SRC; t += 256) {
        float s = bsv;
#pragma unroll
        for (int jb = 0; jb < 8; jb++) s += g_spart[jb * MROWS + b * SRC + t];
        sv[t] = s;
        lmax = fmaxf(lmax, s);
    }
    red[tid] = lmax;
    __syncthreads();
    for (int off = 128; off; off >>= 1) {
        if (tid < off) red[tid] = fmaxf(red[tid], red[tid + off]);
        __syncthreads();
    }
    float m = red[0];
    __syncthreads();
    float lsum = 0.f;
    for (int t = tid; t < SRC; t += 256) {
        float e = expf(sv[t] - m);
        sv[t] = e;
        lsum += e;
    }
    red[tid] = lsum;
    __syncthreads();
    for (int off = 128; off; off >>= 1) {
        if (tid < off) red[tid] += red[tid + off];
        __syncthreads();
    }
    float inv = 1.f / red[0];
    for (int t = tid; t < SRC; t += 256) g_w[b * SRC + t] = sv[t] * inv;
}

// ---------------- k_ctx : ctx[b,k] = sum_t w[b,t]*enc[b,t,k] ----------------
__global__ void k_ctx(const float* __restrict__ enc) {
    __shared__ float sw[SRC];
    int b = blockIdx.y;
    int k = blockIdx.x * 256 + threadIdx.x;
    for (int t = threadIdx.x; t < SRC; t += 256) sw[t] = g_w[b * SRC + t];
    __syncthreads();
    const float* ep = enc + (size_t)b * SRC * ENCD + k;
    float a0 = 0.f, a1 = 0.f, a2 = 0.f, a3 = 0.f;
#pragma unroll 2
    for (int t = 0; t < SRC; t += 4) {
        a0 += sw[t] * ep[(size_t)t * ENCD];
        a1 += sw[t + 1] * ep[(size_t)(t + 1) * ENCD];
        a2 += sw[t + 2] * ep[(size_t)(t + 2) * ENCD];
        a3 += sw[t + 3] * ep[(size_t)(t + 3) * ENCD];
    }
    g_ctx[b * ENCD + k] = (a0 + a1) + (a2 + a3);
}

// ---------------- k_xin : concat(ctx, emb[x]) --------------------------------
__global__ void k_xin(const int* __restrict__ x, const float* __restrict__ emb) {
    int b = blockIdx.x;
    int xi = x[b];
    for (int i = threadIdx.x; i < IN0; i += 256) {
        float v = (i < ENCD) ? g_ctx[b * ENCD + i]
                             : emb[(size_t)xi * EE + (i - ENCD)];
        g_xin[b * IN0 + i] = v;
    }
}

// ---------------- generic tf32 GEMM: C(64xN) = A(64xK) @ B(KxN) [+bias] -----
// block tile 64x128, BK=32, 8 warps of 32x32. K%32==0, N%128==0 required.
template <int EPI>
__global__ __launch_bounds__(256, 2) void k_gemm(const float* __restrict__ A,
                                                 const float* __restrict__ B,
                                                 const float* __restrict__ bias,
                                                 float* __restrict__ C, int K, int N) {
    __shared__ __align__(16) unsigned sA[64 * 36];
    __shared__ __align__(16) unsigned sB[32 * 132];
    const int tid = threadIdx.x;
    const int wid = tid >> 5, lane = tid & 31;
    const int wm = wid & 1, wn = wid >> 1;
    const int g = lane >> 2, tg = lane & 3;
    const int col0 = blockIdx.x * 128;

    float c[2][4][4];
#pragma unroll
    for (int a = 0; a < 2; a++)
#pragma unroll
        for (int b2 = 0; b2 < 4; b2++)
#pragma unroll
            for (int d = 0; d < 4; d++) c[a][b2][d] = 0.f;

    for (int k0 = 0; k0 < K; k0 += 32) {
#pragma unroll
        for (int i = 0; i < 2; i++) {  // A: 64x32
            int idx = tid + i * 256;
            int row = idx >> 3, c4 = idx & 7;
            float4 v = *reinterpret_cast<const float4*>(A + (size_t)row * K + k0 + c4 * 4);
            *reinterpret_cast<uint4*>(&sA[row * 36 + c4 * 4]) = cvt4(v);
        }
#pragma unroll
        for (int i = 0; i < 4; i++) {  // B: 32x128
            int idx = tid + i * 256;
            int rb = idx >> 5, c4 = idx & 31;
            float4 v = *reinterpret_cast<const float4*>(B + (size_t)(k0 + rb) * N + col0 + c4 * 4);
            *reinterpret_cast<uint4*>(&sB[rb * 132 + c4 * 4]) = cvt4(v);
        }
        __syncthreads();
#pragma unroll
        for (int ks = 0; ks < 4; ks++) {
            const int kb = ks * 8;
            unsigned af[2][4], bf[4][2];
#pragma unroll
            for (int mt = 0; mt < 2; mt++) {
                int r = wm * 32 + mt * 16 + g;
                af[mt][0] = sA[r * 36 + kb + tg];
                af[mt][1] = sA[(r + 8) * 36 + kb + tg];
                af[mt][2] = sA[r * 36 + kb + tg + 4];
                af[mt][3] = sA[(r + 8) * 36 + kb + tg + 4];
            }
#pragma unroll
            for (int nt = 0; nt < 4; nt++) {
                int col = wn * 32 + nt * 8 + g;
                bf[nt][0] = sB[(kb + tg) * 132 + col];
                bf[nt][1] = sB[(kb + tg + 4) * 132 + col];
            }
#pragma unroll
            for (int mt = 0; mt < 2; mt++)
#pragma unroll
                for (int nt = 0; nt < 4; nt++) MMA_TF32(c[mt][nt], af[mt], bf[nt]);
        }
        __syncthreads();
    }
#pragma unroll
    for (int mt = 0; mt < 2; mt++)
#pragma unroll
        for (int nt = 0; nt < 4; nt++) {
            int r = wm * 32 + mt * 16 + g;
            int col = col0 + wn * 32 + nt * 8 + tg * 2;
            float add0 = 0.f, add1 = 0.f;
            if (EPI == 1) { add0 = bias[col]; add1 = bias[col + 1]; }
            C[(size_t)r * N + col] = c[mt][nt][0] + add0;
            C[(size_t)r * N + col + 1] = c[mt][nt][1] + add1;
            C[(size_t)(r + 8) * N + col] = c[mt][nt][2] + add0;
            C[(size_t)(r + 8) * N + col + 1] = c[mt][nt][3] + add1;
        }
}

// ---------------- k_gru : pointwise GRU with zero hidden state ---------------
// xg = x@k (no bias yet). b = [b0 (3U), b1 (3U)]. h_out = (1-z)*tanh(xh+b0h+r*b1h)
__global__ void k_gru(const float* __restrict__ xg, const float* __restrict__ bvec,
                      float* __restrict__ hout) {
    int b = blockIdx.x;
    for (int u = threadIdx.x; u < UU; u += 256) {
        float xz = xg[b * 3 * UU + u] + bvec[u] + bvec[3 * UU + u];
        float xr = xg[b * 3 * UU + UU + u] + bvec[UU + u] + bvec[3 * UU + UU + u];
        float xh = xg[b * 3 * UU + 2 * UU + u] + bvec[2 * UU + u];
        float b1h = bvec[3 * UU + 2 * UU + u];
        float z = 1.f / (1.f + expf(-xz));
        float r = 1.f / (1.f + expf(-xr));
        float hc = tanhf(xh + r * b1h);
        hout[b * UU + u] = (1.f - z) * hc;
    }
}

// ---------------- k_concat : y = [h1f, h1b] ----------------------------------
__global__ void k_concat(const float* __restrict__ h1f, const float* __restrict__ h1b) {
    int b = blockIdx.x;
    for (int i = threadIdx.x; i < 2 * UU; i += 256)
        g_y[b * 2 * UU + i] = (i < UU) ? h1f[b * UU + i] : h1b[b * UU + i - UU];
}

// ---------------- host launcher ----------------------------------------------
extern "C" void kernel_launch(void* const* d_in, const int* in_sizes, int n_in,
                              void* d_out, int out_size) {
    (void)in_sizes; (void)n_in; (void)out_size;
    const int* x = (const int*)d_in[0];
    const float* state = (const float*)d_in[1];
    const float* enc = (const float*)d_in[2];
    const float* Wh = (const float*)d_in[3];
    const float* bh = (const float*)d_in[4];
    const float* Wc = (const float*)d_in[5];
    const float* bc = (const float*)d_in[6];
    const float* Ws = (const float*)d_in[7];
    const float* bs = (const float*)d_in[8];
    const float* emb = (const float*)d_in[9];
    const float* fw0_k = (const float*)d_in[10];
    const float* fw0_b = (const float*)d_in[12];
    const float* fw1_k = (const float*)d_in[13];
    const float* fw1_b = (const float*)d_in[15];
    const float* bw0_k = (const float*)d_in[16];
    const float* bw0_b = (const float*)d_in[18];
    const float* bw1_k = (const float*)d_in[19];
    const float* bw1_b = (const float*)d_in[21];
    const float* fcW = (const float*)d_in[22];
    const float* fcb = (const float*)d_in[23];

    float* out = (float*)d_out;
    float* h0f = out + (size_t)BB * VV;    // 2048000
    float* h1f = h0f + BB * UU;
    float* h0b = h1f + BB * UU;
    float* h1b = h0b + BB * UU;

    float *p_xin, *p_xg, *p_y;
    cudaGetSymbolAddress((void**)&p_xin, g_xin);
    cudaGetSymbolAddress((void**)&p_xg, g_xg);
    cudaGetSymbolAddress((void**)&p_y, g_y);

    // attention
    k_h<<<BB, 256>>>(state, Wh, bh);
    k_score<<<dim3(8, MROWS / 128), 256>>>(enc, Wc, bc, Ws);
    k_softmax<<<BB, 256>>>(bs);
    k_ctx<<<dim3(ENCD / 256, BB), 256>>>(enc);
    k_xin<<<BB, 256>>>(x, emb);

    // forward GRU stack (zero hidden state => rk unused)
    k_gemm<0><<<dim3(3 * UU / 128, 1), 256>>>(p_xin, fw0_k, nullptr, p_xg, IN0, 3 * UU);
    k_gru<<<BB, 256>>>(p_xg, fw0_b, h0f);
    k_gemm<0><<<dim3(3 * UU / 128, 1), 256>>>(h0f, fw1_k, nullptr, p_xg, UU, 3 * UU);
    k_gru<<<BB, 256>>>(p_xg, fw1_b, h1f);

    // backward GRU stack
    k_gemm<0><<<dim3(3 * UU / 128, 1), 256>>>(p_xin, bw0_k, nullptr, p_xg, IN0, 3 * UU);
    k_gru<<<BB, 256>>>(p_xg, bw0_b, h0b);
    k_gemm<0><<<dim3(3 * UU / 128, 1), 256>>>(h0b, bw1_k, nullptr, p_xg, UU, 3 * UU);
    k_gru<<<BB, 256>>>(p_xg, bw1_b, h1b);

    // output projection
    k_concat<<<BB, 256>>>(h1f, h1b);
    k_gemm<1><<<dim3(VV / 128, 1), 256>>>(p_y, fcW, fcb, out, 2 * UU, VV);
}

// round 3
// speedup vs baseline: 1.5765x; 1.5765x over previous
#include <cuda_runtime.h>
#include <cuda_fp16.h>
#include <cstdint>

// Problem constants
#define BB   64
#define SRC  2048
#define ENCD 1024
#define UU   1024
#define EE   512
#define VV   32000
#define IN0  (ENCD + EE)        // 1536
#define MROWS (BB * SRC)        // 131072

// ---------------- scratch (device globals; no allocation allowed) -----------
__device__ float  g_h[BB * UU];
__device__ __half g_encH[(size_t)MROWS * ENCD];   // enc in fp16 (256MB)
__device__ __half g_WcTH[ENCD * UU];              // Wc transposed fp16
__device__ float  g_s[MROWS];                     // scores
__device__ float  g_w[BB * SRC];
__device__ float  g_ctxp[8][BB][ENCD];
__device__ float  g_ctx[BB * ENCD];
__device__ float  g_xin[BB * IN0];
__device__ float  g_xg[2][BB * 3 * UU];
__device__ float  g_y[BB * 2 * UU];

// ---------------- helpers ----------------------------------------------------
__device__ __forceinline__ unsigned f2tf32(float f) {
    unsigned u;
    asm("cvt.rna.tf32.f32 %0, %1;" : "=r"(u) : "f"(f));
    return u;
}
__device__ __forceinline__ uint4 cvt4(float4 v) {
    uint4 u;
    u.x = f2tf32(v.x); u.y = f2tf32(v.y); u.z = f2tf32(v.z); u.w = f2tf32(v.w);
    return u;
}
__device__ __forceinline__ float htanh(float x) {
    float r;
    asm("tanh.approx.f32 %0, %1;" : "=f"(r) : "f"(x));
    return r;
}
__device__ __forceinline__ uint32_t smem_u32(const void* p) {
    uint32_t a;
    asm("{ .reg .u64 t; cvta.to.shared.u64 t, %1; cvt.u32.u64 %0, t; }" : "=r"(a) : "l"(p));
    return a;
}
__device__ __forceinline__ void cp16(uint32_t dst, const void* src) {
    asm volatile("cp.async.cg.shared.global [%0], [%1], 16;\n" :: "r"(dst), "l"(src));
}
#define CP_COMMIT() asm volatile("cp.async.commit_group;" ::: "memory")
#define CP_WAIT1()  asm volatile("cp.async.wait_group 1;" ::: "memory")

// fp16 mma m16n8k16 with fp32 accumulate
#define MMA_F16(c, a, b)                                                         \
    asm volatile(                                                                \
        "mma.sync.aligned.m16n8k16.row.col.f32.f16.f16.f32 "                     \
        "{%0,%1,%2,%3},{%4,%5,%6,%7},{%8,%9},{%0,%1,%2,%3};\n"                   \
        : "+f"((c)[0]), "+f"((c)[1]), "+f"((c)[2]), "+f"((c)[3])                 \
        : "r"((a)[0]), "r"((a)[1]), "r"((a)[2]), "r"((a)[3]),                    \
          "r"((b)[0]), "r"((b)[1]))

// tf32 mma m16n8k8 (small GEMMs)
#define MMA_TF32(c, a, b)                                                        \
    asm volatile(                                                                \
        "mma.sync.aligned.m16n8k8.row.col.f32.tf32.tf32.f32 "                    \
        "{%0,%1,%2,%3},{%4,%5,%6,%7},{%8,%9},{%0,%1,%2,%3};\n"                   \
        : "+f"((c)[0]), "+f"((c)[1]), "+f"((c)[2]), "+f"((c)[3])                 \
        : "r"((a)[0]), "r"((a)[1]), "r"((a)[2]), "r"((a)[3]),                    \
          "r"((b)[0]), "r"((b)[1]))

// ---------------- k_enc2h : enc fp32 -> fp16 ---------------------------------
__global__ void k_enc2h(const float* __restrict__ enc) {
    size_t i = ((size_t)blockIdx.x * 256 + threadIdx.x) * 8;
    float4 v0 = *reinterpret_cast<const float4*>(enc + i);
    float4 v1 = *reinterpret_cast<const float4*>(enc + i + 4);
    __half2 h[4];
    h[0] = __floats2half2_rn(v0.x, v0.y);
    h[1] = __floats2half2_rn(v0.z, v0.w);
    h[2] = __floats2half2_rn(v1.x, v1.y);
    h[3] = __floats2half2_rn(v1.z, v1.w);
    *reinterpret_cast<uint4*>(&g_encH[i]) = *reinterpret_cast<uint4*>(h);
}

// ---------------- k_transpose : WcTH[j,k] = (half)Wc[k,j] --------------------
__global__ void k_transpose(const float* __restrict__ Wc) {
    __shared__ float t[32][33];
    int j0 = blockIdx.x * 32, k0 = blockIdx.y * 32;
#pragma unroll
    for (int i = 0; i < 4; i++) {
        int kk = threadIdx.y + i * 8;
        t[kk][threadIdx.x] = Wc[(size_t)(k0 + kk) * UU + j0 + threadIdx.x];
    }
    __syncthreads();
#pragma unroll
    for (int i = 0; i < 4; i++) {
        int jj = threadIdx.y + i * 8;
        g_WcTH[(size_t)(j0 + jj) * ENCD + k0 + threadIdx.x] =
            __float2half_rn(t[threadIdx.x][jj]);
    }
}

// ---------------- k_h : h = state @ att_Wh + bh  (64 x 1024) ----------------
__global__ void k_h(const float* __restrict__ state, const float* __restrict__ Wh,
                    const float* __restrict__ bh) {
    int b = blockIdx.x;
    __shared__ float ss[UU];
    for (int i = threadIdx.x; i < UU; i += 256) ss[i] = state[b * UU + i];
    __syncthreads();
    float acc[4] = {0.f, 0.f, 0.f, 0.f};
#pragma unroll 4
    for (int k = 0; k < UU; k++) {
        float sv = ss[k];
        const float* wr = Wh + (size_t)k * UU + threadIdx.x;
        acc[0] += sv * wr[0];
        acc[1] += sv * wr[256];
        acc[2] += sv * wr[512];
        acc[3] += sv * wr[768];
    }
#pragma unroll
    for (int jj = 0; jj < 4; jj++) {
        int j = threadIdx.x + jj * 256;
        g_h[b * UU + j] = acc[jj] + bh[j];
    }
}

// ---------------- k_score : fp16 mma, A-resident, fused tanh reduction ------
// one CTA per 128-row block; loops all 8 j-tiles of 128; BK=32, 2-stage cp.async
#define SKW 20   // smem row stride in 32-bit words (16 data + 4 pad)
__global__ __launch_bounds__(256, 2) void k_score(const float* __restrict__ bc,
                                                  const float* __restrict__ Ws) {
    __shared__ uint32_t sA[2][128 * SKW];
    __shared__ uint32_t sB[2][128 * SKW];
    __shared__ float shb[128], sws[128], srow[128];

    const int tid = threadIdx.x, wid = tid >> 5, lane = tid & 31;
    const int wm = wid & 1, wn = wid >> 1;
    const int g = lane >> 2, tg = lane & 3;
    const int R0 = blockIdx.x * 128;
    const int bidx = blockIdx.x >> 4;      // 2048 rows per batch element

    if (tid < 128) srow[tid] = 0.f;

    const uint32_t sA0 = smem_u32(&sA[0][0]);
    const uint32_t sB0 = smem_u32(&sB[0][0]);
    const __half* aBase = g_encH + (size_t)R0 * ENCD;

    // loader: stage s, k-chunk kc, j-tile jt (A independent of jt)
    auto load_stage = [&](int s, int jt, int kc) {
        const __half* aSrc = aBase + kc * 32;
        const __half* bSrc = g_WcTH + (size_t)(jt * 128) * ENCD + kc * 32;
        uint32_t aDst = sA0 + s * (128 * SKW * 4);
        uint32_t bDst = sB0 + s * (128 * SKW * 4);
#pragma unroll
        for (int i = 0; i < 2; i++) {
            int idx = tid + i * 256;        // 0..511
            int row = idx >> 2, seg = idx & 3;
            cp16(aDst + (row * SKW + seg * 4) * 4, aSrc + (size_t)row * ENCD + seg * 8);
            cp16(bDst + (row * SKW + seg * 4) * 4, bSrc + (size_t)row * ENCD + seg * 8);
        }
    };

    float rowacc[4][2] = {{0.f, 0.f}, {0.f, 0.f}, {0.f, 0.f}, {0.f, 0.f}};

    for (int jt = 0; jt < 8; jt++) {
        __syncthreads();   // previous epilogue done with shb/sws
        if (tid < 128) {
            int j = jt * 128 + tid;
            shb[tid] = g_h[bidx * UU + j] + bc[j];
            sws[tid] = Ws[j];
        }

        float c[4][4][4];
#pragma unroll
        for (int a = 0; a < 4; a++)
#pragma unroll
            for (int b2 = 0; b2 < 4; b2++)
#pragma unroll
                for (int d = 0; d < 4; d++) c[a][b2][d] = 0.f;

        load_stage(0, jt, 0);
        CP_COMMIT();

        for (int kc = 0; kc < 32; kc++) {
            int s = kc & 1;
            if (kc + 1 < 32) load_stage(s ^ 1, jt, kc + 1);
            CP_COMMIT();
            CP_WAIT1();
            __syncthreads();

            const uint32_t* pA = &sA[s][0];
            const uint32_t* pB = &sB[s][0];
#pragma unroll
            for (int ks = 0; ks < 2; ks++) {
                const int kb = ks * 8;
                uint32_t bf[4][2];
#pragma unroll
                for (int nt = 0; nt < 4; nt++) {
                    int n = wn * 32 + nt * 8 + g;
                    bf[nt][0] = pB[n * SKW + kb + tg];
                    bf[nt][1] = pB[n * SKW + kb + tg + 4];
                }
#pragma unroll
                for (int mt = 0; mt < 4; mt++) {
                    int r = wm * 64 + mt * 16 + g;
                    uint32_t af[4];
                    af[0] = pA[r * SKW + kb + tg];
                    af[1] = pA[(r + 8) * SKW + kb + tg];
                    af[2] = pA[r * SKW + kb + tg + 4];
                    af[3] = pA[(r + 8) * SKW + kb + tg + 4];
#pragma unroll
                    for (int nt = 0; nt < 4; nt++) MMA_F16(c[mt][nt], af, bf[nt]);
                }
            }
            __syncthreads();
        }

        // epilogue: accumulate tanh(c + hb) * ws into per-row partials
#pragma unroll
        for (int mt = 0; mt < 4; mt++) {
            float rs0 = 0.f, rs1 = 0.f;
#pragma unroll
            for (int nt = 0; nt < 4; nt++) {
                int nl = wn * 32 + nt * 8 + tg * 2;
#pragma unroll
                for (int cc = 0; cc < 2; cc++) {
                    float hb = shb[nl + cc], ws = sws[nl + cc];
                    rs0 += htanh(c[mt][nt][cc] + hb) * ws;
                    rs1 += htanh(c[mt][nt][2 + cc] + hb) * ws;
                }
            }
            rs0 += __shfl_xor_sync(0xffffffffu, rs0, 1);
            rs0 += __shfl_xor_sync(0xffffffffu, rs0, 2);
            rs1 += __shfl_xor_sync(0xffffffffu, rs1, 1);
            rs1 += __shfl_xor_sync(0xffffffffu, rs1, 2);
            rowacc[mt][0] += rs0;
            rowacc[mt][1] += rs1;
        }
    }

    // cross-warp (wn) reduction via smem atomics
#pragma unroll
    for (int mt = 0; mt < 4; mt++) {
        if (tg == 0) {
            atomicAdd(&srow[wm * 64 + mt * 16 + g], rowacc[mt][0]);
            atomicAdd(&srow[wm * 64 + mt * 16 + 8 + g], rowacc[mt][1]);
        }
    }
    __syncthreads();
    if (tid < 128) g_s[R0 + tid] = srow[tid];
}

// ---------------- k_softmax ---------------------------------------------------
__global__ void k_softmax(const float* __restrict__ bs) {
    __shared__ float sv[SRC];
    __shared__ float red[256];
    int b = blockIdx.x, tid = threadIdx.x;
    float bsv = bs[0];
    float lmax = -1e30f;
    for (int t = tid; t < SRC; t += 256) {
        float s = bsv + g_s[b * SRC + t];
        sv[t] = s;
        lmax = fmaxf(lmax, s);
    }
    red[tid] = lmax;
    __syncthreads();
    for (int off = 128; off; off >>= 1) {
        if (tid < off) red[tid] = fmaxf(red[tid], red[tid + off]);
        __syncthreads();
    }
    float m = red[0];
    __syncthreads();
    float lsum = 0.f;
    for (int t = tid; t < SRC; t += 256) {
        float e = expf(sv[t] - m);
        sv[t] = e;
        lsum += e;
    }
    red[tid] = lsum;
    __syncthreads();
    for (int off = 128; off; off >>= 1) {
        if (tid < off) red[tid] += red[tid + off];
        __syncthreads();
    }
    float inv = 1.f / red[0];
    for (int t = tid; t < SRC; t += 256) g_w[b * SRC + t] = sv[t] * inv;
}

// ---------------- k_ctx : segmented weighted sum -----------------------------
__global__ void k_ctx(const float* __restrict__ enc) {
    __shared__ float sw[256];
    int b = blockIdx.y, seg = blockIdx.z;
    int k = blockIdx.x * 256 + threadIdx.x;
    int t0 = seg * 256;
    sw[threadIdx.x] = g_w[b * SRC + t0 + threadIdx.x];
    __syncthreads();
    const float* ep = enc + ((size_t)b * SRC + t0) * ENCD + k;
    float a0 = 0.f, a1 = 0.f, a2 = 0.f, a3 = 0.f;
#pragma unroll 4
    for (int t = 0; t < 256; t += 4) {
        a0 += sw[t] * ep[(size_t)t * ENCD];
        a1 += sw[t + 1] * ep[(size_t)(t + 1) * ENCD];
        a2 += sw[t + 2] * ep[(size_t)(t + 2) * ENCD];
        a3 += sw[t + 3] * ep[(size_t)(t + 3) * ENCD];
    }
    g_ctxp[seg][b][k] = (a0 + a1) + (a2 + a3);
}

__global__ void k_ctx_red() {
    int i = blockIdx.x * 256 + threadIdx.x;
    const float* p = &g_ctxp[0][0][0];
    float s = 0.f;
#pragma unroll
    for (int seg = 0; seg < 8; seg++) s += p[seg * BB * ENCD + i];
    g_ctx[i] = s;
}

// ---------------- k_xin -------------------------------------------------------
__global__ void k_xin(const int* __restrict__ x, const float* __restrict__ emb) {
    int b = blockIdx.x;
    int xi = x[b];
    for (int i = threadIdx.x; i < IN0; i += 256) {
        float v = (i < ENCD) ? g_ctx[b * ENCD + i]
                             : emb[(size_t)xi * EE + (i - ENCD)];
        g_xin[b * IN0 + i] = v;
    }
}

// ---------------- legacy tf32 GEMM body: C(64xN) = A(64xK)@B(KxN) [+bias] ---
template <int EPI>
__device__ __forceinline__ void gemm_body(const float* __restrict__ A,
                                          const float* __restrict__ B,
                                          const float* __restrict__ bias,
                                          float* __restrict__ C, int K, int N,
                                          int col0) {
    __shared__ __align__(16) unsigned sA[64 * 36];
    __shared__ __align__(16) unsigned sB[32 * 132];
    const int tid = threadIdx.x;
    const int wid = tid >> 5, lane = tid & 31;
    const int wm = wid & 1, wn = wid >> 1;
    const int g = lane >> 2, tg = lane & 3;

    float c[2][4][4];
#pragma unroll
    for (int a = 0; a < 2; a++)
#pragma unroll
        for (int b2 = 0; b2 < 4; b2++)
#pragma unroll
            for (int d = 0; d < 4; d++) c[a][b2][d] = 0.f;

    for (int k0 = 0; k0 < K; k0 += 32) {
#pragma unroll
        for (int i = 0; i < 2; i++) {
            int idx = tid + i * 256;
            int row = idx >> 3, c4 = idx & 7;
            float4 v = *reinterpret_cast<const float4*>(A + (size_t)row * K + k0 + c4 * 4);
            *reinterpret_cast<uint4*>(&sA[row * 36 + c4 * 4]) = cvt4(v);
        }
#pragma unroll
        for (int i = 0; i < 4; i++) {
            int idx = tid + i * 256;
            int rb = idx >> 5, c4 = idx & 31;
            float4 v = *reinterpret_cast<const float4*>(B + (size_t)(k0 + rb) * N + col0 + c4 * 4);
            *reinterpret_cast<uint4*>(&sB[rb * 132 + c4 * 4]) = cvt4(v);
        }
        __syncthreads();
#pragma unroll
        for (int ks = 0; ks < 4; ks++) {
            const int kb = ks * 8;
            unsigned af[2][4], bf[4][2];
#pragma unroll
            for (int mt = 0; mt < 2; mt++) {
                int r = wm * 32 + mt * 16 + g;
                af[mt][0] = sA[r * 36 + kb + tg];
                af[mt][1] = sA[(r + 8) * 36 + kb + tg];
                af[mt][2] = sA[r * 36 + kb + tg + 4];
                af[mt][3] = sA[(r + 8) * 36 + kb + tg + 4];
            }
#pragma unroll
            for (int nt = 0; nt < 4; nt++) {
                int col = wn * 32 + nt * 8 + g;
                bf[nt][0] = sB[(kb + tg) * 132 + col];
                bf[nt][1] = sB[(kb + tg + 4) * 132 + col];
            }
#pragma unroll
            for (int mt = 0; mt < 2; mt++)
#pragma unroll
                for (int nt = 0; nt < 4; nt++) MMA_TF32(c[mt][nt], af[mt], bf[nt]);
        }
        __syncthreads();
    }
#pragma unroll
    for (int mt = 0; mt < 2; mt++)
#pragma unroll
        for (int nt = 0; nt < 4; nt++) {
            int r = wm * 32 + mt * 16 + g;
            int col = col0 + wn * 32 + nt * 8 + tg * 2;
            float add0 = 0.f, add1 = 0.f;
            if (EPI == 1) { add0 = bias[col]; add1 = bias[col + 1]; }
            C[(size_t)r * N + col] = c[mt][nt][0] + add0;
            C[(size_t)r * N + col + 1] = c[mt][nt][1] + add1;
            C[(size_t)(r + 8) * N + col] = c[mt][nt][2] + add0;
            C[(size_t)(r + 8) * N + col + 1] = c[mt][nt][3] + add1;
        }
}

template <int EPI>
__global__ __launch_bounds__(256, 2) void k_gemm(const float* __restrict__ A,
                                                 const float* __restrict__ B,
                                                 const float* __restrict__ bias,
                                                 float* __restrict__ C, int K, int N) {
    gemm_body<EPI>(A, B, bias, C, K, N, blockIdx.x * 128);
}

__global__ __launch_bounds__(256, 2) void k_gemm_pair(
    const float* A0, const float* A1, const float* B0, const float* B1,
    float* C0, float* C1, int K, int N) {
    const float* A = blockIdx.y ? A1 : A0;
    const float* B = blockIdx.y ? B1 : B0;
    float* C = blockIdx.y ? C1 : C0;
    gemm_body<0>(A, B, nullptr, C, K, N, blockIdx.x * 128);
}

// ---------------- k_gru_pair : pointwise GRU, zero hidden state -------------
__global__ void k_gru_pair(const float* xg0, const float* xg1,
                           const float* b0v, const float* b1v,
                           float* o0, float* o1) {
    const float* xg = blockIdx.y ? xg1 : xg0;
    const float* bvec = blockIdx.y ? b1v : b0v;
    float* hout = blockIdx.y ? o1 : o0;
    int b = blockIdx.x;
    for (int u = threadIdx.x; u < UU; u += 256) {
        float xz = xg[b * 3 * UU + u] + bvec[u] + bvec[3 * UU + u];
        float xr = xg[b * 3 * UU + UU + u] + bvec[UU + u] + bvec[3 * UU + UU + u];
        float xh = xg[b * 3 * UU + 2 * UU + u] + bvec[2 * UU + u];
        float b1h = bvec[3 * UU + 2 * UU + u];
        float z = 1.f / (1.f + expf(-xz));
        float r = 1.f / (1.f + expf(-xr));
        float hc = tanhf(xh + r * b1h);
        hout[b * UU + u] = (1.f - z) * hc;
    }
}

// ---------------- k_concat ----------------------------------------------------
__global__ void k_concat(const float* __restrict__ h1f, const float* __restrict__ h1b) {
    int b = blockIdx.x;
    for (int i = threadIdx.x; i < 2 * UU; i += 256)
        g_y[b * 2 * UU + i] = (i < UU) ? h1f[b * UU + i] : h1b[b * UU + i - UU];
}

// ---------------- host launcher ----------------------------------------------
extern "C" void kernel_launch(void* const* d_in, const int* in_sizes, int n_in,
                              void* d_out, int out_size) {
    (void)in_sizes; (void)n_in; (void)out_size;
    const int* x = (const int*)d_in[0];
    const float* state = (const float*)d_in[1];
    const float* enc = (const float*)d_in[2];
    const float* Wh = (const float*)d_in[3];
    const float* bh = (const float*)d_in[4];
    const float* Wc = (const float*)d_in[5];
    const float* bc = (const float*)d_in[6];
    const float* Ws = (const float*)d_in[7];
    const float* bs = (const float*)d_in[8];
    const float* emb = (const float*)d_in[9];
    const float* fw0_k = (const float*)d_in[10];
    const float* fw0_b = (const float*)d_in[12];
    const float* fw1_k = (const float*)d_in[13];
    const float* fw1_b = (const float*)d_in[15];
    const float* bw0_k = (const float*)d_in[16];
    const float* bw0_b = (const float*)d_in[18];
    const float* bw1_k = (const float*)d_in[19];
    const float* bw1_b = (const float*)d_in[21];
    const float* fcW = (const float*)d_in[22];
    const float* fcb = (const float*)d_in[23];

    float* out = (float*)d_out;
    float* h0f = out + (size_t)BB * VV;
    float* h1f = h0f + BB * UU;
    float* h0b = h1f + BB * UU;
    float* h1b = h0b + BB * UU;

    float *p_xin, *p_xg0, *p_xg1, *p_y;
    cudaGetSymbolAddress((void**)&p_xin, g_xin);
    cudaGetSymbolAddress((void**)&p_xg0, g_xg);
    p_xg1 = p_xg0 + BB * 3 * UU;
    cudaGetSymbolAddress((void**)&p_y, g_y);

    // attention
    k_enc2h<<<(size_t)MROWS * ENCD / (256 * 8), 256>>>(enc);
    k_transpose<<<dim3(32, 32), dim3(32, 8)>>>(Wc);
    k_h<<<BB, 256>>>(state, Wh, bh);
    k_score<<<MROWS / 128, 256>>>(bc, Ws);
    k_softmax<<<BB, 256>>>(bs);
    k_ctx<<<dim3(ENCD / 256, BB, 8), 256>>>(enc);
    k_ctx_red<<<BB * ENCD / 256, 256>>>();
    k_xin<<<BB, 256>>>(x, emb);

    // GRU stacks (zero hidden state => rk unused); fw/bw paired
    k_gemm_pair<<<dim3(3 * UU / 128, 2), 256>>>(p_xin, p_xin, fw0_k, bw0_k,
                                                p_xg0, p_xg1, IN0, 3 * UU);
    k_gru_pair<<<dim3(BB, 2), 256>>>(p_xg0, p_xg1, fw0_b, bw0_b, h0f, h0b);
    k_gemm_pair<<<dim3(3 * UU / 128, 2), 256>>>(h0f, h0b, fw1_k, bw1_k,
                                                p_xg0, p_xg1, UU, 3 * UU);
    k_gru_pair<<<dim3(BB, 2), 256>>>(p_xg0, p_xg1, fw1_b, bw1_b, h1f, h1b);

    // output projection
    k_concat<<<BB, 256>>>(h1f, h1b);
    k_gemm<1><<<dim3(VV / 128, 1), 256>>>(p_y, fcW, fcb, out, 2 * UU, VV);
}

// round 4
// speedup vs baseline: 1.7341x; 1.1000x over previous
#include <cuda_runtime.h>
#include <cuda_fp16.h>
#include <cstdint>

// Problem constants
#define BB   64
#define SRC  2048
#define ENCD 1024
#define UU   1024
#define EE   512
#define VV   32000
#define IN0  (ENCD + EE)        // 1536
#define MROWS (BB * SRC)        // 131072

// ---------------- scratch (device globals; no allocation allowed) -----------
__device__ float  g_h[BB * UU];
__device__ __half g_encH[(size_t)MROWS * ENCD];   // enc in fp16 (256MB)
__device__ __half g_WcTH[ENCD * UU];              // Wc transposed fp16
__device__ float  g_s[MROWS];                     // scores
__device__ float  g_w[BB * SRC];
__device__ float  g_ctxp[8][BB][ENCD];
__device__ float  g_ctx[BB * ENCD];
__device__ float  g_xin[BB * IN0];
__device__ float  g_xg[2][BB * 3 * UU];
__device__ float  g_y[BB * 2 * UU];

// ---------------- helpers ----------------------------------------------------
__device__ __forceinline__ unsigned f2tf32(float f) {
    unsigned u;
    asm("cvt.rna.tf32.f32 %0, %1;" : "=r"(u) : "f"(f));
    return u;
}
__device__ __forceinline__ uint4 cvt4(float4 v) {
    uint4 u;
    u.x = f2tf32(v.x); u.y = f2tf32(v.y); u.z = f2tf32(v.z); u.w = f2tf32(v.w);
    return u;
}
__device__ __forceinline__ float htanh(float x) {
    float r;
    asm("tanh.approx.f32 %0, %1;" : "=f"(r) : "f"(x));
    return r;
}
__device__ __forceinline__ uint32_t smem_u32(const void* p) {
    uint32_t a;
    asm("{ .reg .u64 t; cvta.to.shared.u64 t, %1; cvt.u32.u64 %0, t; }" : "=r"(a) : "l"(p));
    return a;
}
__device__ __forceinline__ void cp16(uint32_t dst, const void* src) {
    asm volatile("cp.async.cg.shared.global [%0], [%1], 16;\n" :: "r"(dst), "l"(src));
}
#define CP_COMMIT() asm volatile("cp.async.commit_group;" ::: "memory")
#define CP_WAIT1()  asm volatile("cp.async.wait_group 1;" ::: "memory")

#define LDSM4(r0, r1, r2, r3, addr)                                              \
    asm volatile("ldmatrix.sync.aligned.m8n8.x4.shared.b16 {%0,%1,%2,%3}, [%4];" \
                 : "=r"(r0), "=r"(r1), "=r"(r2), "=r"(r3) : "r"(addr))

// fp16 mma m16n8k16 with fp32 accumulate
#define MMA_F16(c, a, b)                                                         \
    asm volatile(                                                                \
        "mma.sync.aligned.m16n8k16.row.col.f32.f16.f16.f32 "                     \
        "{%0,%1,%2,%3},{%4,%5,%6,%7},{%8,%9},{%0,%1,%2,%3};\n"                   \
        : "+f"((c)[0]), "+f"((c)[1]), "+f"((c)[2]), "+f"((c)[3])                 \
        : "r"((a)[0]), "r"((a)[1]), "r"((a)[2]), "r"((a)[3]),                    \
          "r"((b)[0]), "r"((b)[1]))

// tf32 mma m16n8k8 (small GEMMs)
#define MMA_TF32(c, a, b)                                                        \
    asm volatile(                                                                \
        "mma.sync.aligned.m16n8k8.row.col.f32.tf32.tf32.f32 "                    \
        "{%0,%1,%2,%3},{%4,%5,%6,%7},{%8,%9},{%0,%1,%2,%3};\n"                   \
        : "+f"((c)[0]), "+f"((c)[1]), "+f"((c)[2]), "+f"((c)[3])                 \
        : "r"((a)[0]), "r"((a)[1]), "r"((a)[2]), "r"((a)[3]),                    \
          "r"((b)[0]), "r"((b)[1]))

// ---------------- k_enc2h : enc fp32 -> fp16 ---------------------------------
__global__ void k_enc2h(const float* __restrict__ enc) {
    size_t i = ((size_t)blockIdx.x * 256 + threadIdx.x) * 8;
    float4 v0 = *reinterpret_cast<const float4*>(enc + i);
    float4 v1 = *reinterpret_cast<const float4*>(enc + i + 4);
    __half2 h[4];
    h[0] = __floats2half2_rn(v0.x, v0.y);
    h[1] = __floats2half2_rn(v0.z, v0.w);
    h[2] = __floats2half2_rn(v1.x, v1.y);
    h[3] = __floats2half2_rn(v1.z, v1.w);
    *reinterpret_cast<uint4*>(&g_encH[i]) = *reinterpret_cast<uint4*>(h);
}

// ---------------- k_transpose : WcTH[j,k] = (half)Wc[k,j] --------------------
__global__ void k_transpose(const float* __restrict__ Wc) {
    __shared__ float t[32][33];
    int j0 = blockIdx.x * 32, k0 = blockIdx.y * 32;
#pragma unroll
    for (int i = 0; i < 4; i++) {
        int kk = threadIdx.y + i * 8;
        t[kk][threadIdx.x] = Wc[(size_t)(k0 + kk) * UU + j0 + threadIdx.x];
    }
    __syncthreads();
#pragma unroll
    for (int i = 0; i < 4; i++) {
        int jj = threadIdx.y + i * 8;
        g_WcTH[(size_t)(j0 + jj) * ENCD + k0 + threadIdx.x] =
            __float2half_rn(t[threadIdx.x][jj]);
    }
}

// ---------------- k_h : h = state @ att_Wh + bh  (64 x 1024) ----------------
__global__ void k_h(const float* __restrict__ state, const float* __restrict__ Wh,
                    const float* __restrict__ bh) {
    int b = blockIdx.x;
    __shared__ float ss[UU];
    for (int i = threadIdx.x; i < UU; i += 256) ss[i] = state[b * UU + i];
    __syncthreads();
    float acc[4] = {0.f, 0.f, 0.f, 0.f};
#pragma unroll 4
    for (int k = 0; k < UU; k++) {
        float sv = ss[k];
        const float* wr = Wh + (size_t)k * UU + threadIdx.x;
        acc[0] += sv * wr[0];
        acc[1] += sv * wr[256];
        acc[2] += sv * wr[512];
        acc[3] += sv * wr[768];
    }
#pragma unroll
    for (int jj = 0; jj < 4; jj++) {
        int j = threadIdx.x + jj * 256;
        g_h[b * UU + j] = acc[jj] + bh[j];
    }
}

// ---------------- k_score : fp16 mma, flattened single-sync 3-stage pipeline -
// one CTA per 128-row block; 8 j-tiles x 32 k-chunks = 256 pipeline iterations
#define SKW 20                   // smem row stride in 32-bit words (16 data + 4 pad)
#define NST 3
#define STGW (128 * SKW)         // words per stage per array
#define STGB (STGW * 4)          // bytes per stage per array
#define SC_SMEM (2 * NST * STGB + 3 * 128 * 4)

__global__ __launch_bounds__(256, 2) void k_score(const float* __restrict__ bc,
                                                  const float* __restrict__ Ws) {
    extern __shared__ char dsm[];
    uint32_t* sAp = reinterpret_cast<uint32_t*>(dsm);
    uint32_t* sBp = sAp + NST * STGW;
    float* shb = reinterpret_cast<float*>(sBp + NST * STGW);
    float* sws = shb + 128;
    float* srow = sws + 128;

    const int tid = threadIdx.x, wid = tid >> 5, lane = tid & 31;
    const int wm = wid & 1, wn = wid >> 1;
    const int g = lane >> 2, tg = lane & 3;
    const int R0 = blockIdx.x * 128;
    const int bidx = blockIdx.x >> 4;      // 2048 rows per batch element

    if (tid < 128) srow[tid] = 0.f;

    const uint32_t sA0 = smem_u32(sAp);
    const uint32_t sB0 = smem_u32(sBp);
    const __half* aBase = g_encH + (size_t)R0 * ENCD;

    // ldmatrix per-lane byte offsets within a stage
    uint32_t aOff[4], bOff[2];
#pragma unroll
    for (int mt = 0; mt < 4; mt++) {
        int row = wm * 64 + mt * 16 + ((lane >> 3) & 1) * 8 + (lane & 7);
        aOff[mt] = (row * SKW + ((lane >> 4) << 2)) * 4;
    }
#pragma unroll
    for (int np = 0; np < 2; np++) {
        int row = wn * 32 + np * 16 + ((lane >> 4) & 1) * 8 + (lane & 7);
        bOff[np] = (row * SKW + (((lane >> 3) & 1) << 2)) * 4;
    }

    // stage loader for pipeline iteration 'it'
    auto load_it = [&](int it) {
        int kc = it & 31, jt = it >> 5, s = it % NST;
        const __half* aSrc = aBase + kc * 32;
        const __half* bSrc = g_WcTH + (size_t)(jt * 128) * ENCD + kc * 32;
        uint32_t aDst = sA0 + s * STGB;
        uint32_t bDst = sB0 + s * STGB;
#pragma unroll
        for (int i = 0; i < 2; i++) {
            int idx = tid + i * 256;        // 0..511
            int row = idx >> 2, seg = idx & 3;
            cp16(aDst + (row * SKW + seg * 4) * 4, aSrc + (size_t)row * ENCD + seg * 8);
            cp16(bDst + (row * SKW + seg * 4) * 4, bSrc + (size_t)row * ENCD + seg * 8);
        }
    };

    float c[4][4][4];
#pragma unroll
    for (int a = 0; a < 4; a++)
#pragma unroll
        for (int b2 = 0; b2 < 4; b2++)
#pragma unroll
            for (int d = 0; d < 4; d++) c[a][b2][d] = 0.f;
    float rowacc[4][2] = {{0.f, 0.f}, {0.f, 0.f}, {0.f, 0.f}, {0.f, 0.f}};

    load_it(0); CP_COMMIT();
    load_it(1); CP_COMMIT();

    const int TOT = 256;
    for (int it = 0; it < TOT; it++) {
        const int kc = it & 31, jt = it >> 5, s = it % NST;
        CP_WAIT1();
        __syncthreads();

        if (kc == 0 && tid < 128) {
            int j = jt * 128 + tid;
            shb[tid] = g_h[bidx * UU + j] + bc[j];
            sws[tid] = Ws[j];
        }

        if (it + 2 < TOT) load_it(it + 2);
        CP_COMMIT();

        const uint32_t aB = sA0 + s * STGB;
        const uint32_t bB = sB0 + s * STGB;
#pragma unroll
        for (int ks = 0; ks < 2; ks++) {
            uint32_t bf[4][2];
#pragma unroll
            for (int np = 0; np < 2; np++)
                LDSM4(bf[2 * np][0], bf[2 * np][1], bf[2 * np + 1][0], bf[2 * np + 1][1],
                      bB + bOff[np] + ks * 32);
#pragma unroll
            for (int mt = 0; mt < 4; mt++) {
                uint32_t af[4];
                LDSM4(af[0], af[1], af[2], af[3], aB + aOff[mt] + ks * 32);
#pragma unroll
                for (int nt = 0; nt < 4; nt++) MMA_F16(c[mt][nt], af, bf[nt]);
            }
        }

        if (kc == 31) {
            // epilogue for this j-tile: accumulate tanh(c + hb) * ws per row
#pragma unroll
            for (int mt = 0; mt < 4; mt++) {
                float rs0 = 0.f, rs1 = 0.f;
#pragma unroll
                for (int nt = 0; nt < 4; nt++) {
                    int nl = wn * 32 + nt * 8 + tg * 2;
#pragma unroll
                    for (int cc = 0; cc < 2; cc++) {
                        float hb = shb[nl + cc], ws = sws[nl + cc];
                        rs0 += htanh(c[mt][nt][cc] + hb) * ws;
                        rs1 += htanh(c[mt][nt][2 + cc] + hb) * ws;
                    }
                }
                rs0 += __shfl_xor_sync(0xffffffffu, rs0, 1);
                rs0 += __shfl_xor_sync(0xffffffffu, rs0, 2);
                rs1 += __shfl_xor_sync(0xffffffffu, rs1, 1);
                rs1 += __shfl_xor_sync(0xffffffffu, rs1, 2);
                rowacc[mt][0] += rs0;
                rowacc[mt][1] += rs1;
#pragma unroll
                for (int nt = 0; nt < 4; nt++)
#pragma unroll
                    for (int d = 0; d < 4; d++) c[mt][nt][d] = 0.f;
            }
        }
    }

    // cross-warp (wn) reduction via smem atomics
#pragma unroll
    for (int mt = 0; mt < 4; mt++) {
        if (tg == 0) {
            atomicAdd(&srow[wm * 64 + mt * 16 + g], rowacc[mt][0]);
            atomicAdd(&srow[wm * 64 + mt * 16 + 8 + g], rowacc[mt][1]);
        }
    }
    __syncthreads();
    if (tid < 128) g_s[R0 + tid] = srow[tid];
}

// ---------------- k_softmax ---------------------------------------------------
__global__ void k_softmax(const float* __restrict__ bs) {
    __shared__ float sv[SRC];
    __shared__ float red[256];
    int b = blockIdx.x, tid = threadIdx.x;
    float bsv = bs[0];
    float lmax = -1e30f;
    for (int t = tid; t < SRC; t += 256) {
        float s = bsv + g_s[b * SRC + t];
        sv[t] = s;
        lmax = fmaxf(lmax, s);
    }
    red[tid] = lmax;
    __syncthreads();
    for (int off = 128; off; off >>= 1) {
        if (tid < off) red[tid] = fmaxf(red[tid], red[tid + off]);
        __syncthreads();
    }
    float m = red[0];
    __syncthreads();
    float lsum = 0.f;
    for (int t = tid; t < SRC; t += 256) {
        float e = expf(sv[t] - m);
        sv[t] = e;
        lsum += e;
    }
    red[tid] = lsum;
    __syncthreads();
    for (int off = 128; off; off >>= 1) {
        if (tid < off) red[tid] += red[tid + off];
        __syncthreads();
    }
    float inv = 1.f / red[0];
    for (int t = tid; t < SRC; t += 256) g_w[b * SRC + t] = sv[t] * inv;
}

// ---------------- k_ctx : segmented weighted sum -----------------------------
__global__ void k_ctx(const float* __restrict__ enc) {
    __shared__ float sw[256];
    int b = blockIdx.y, seg = blockIdx.z;
    int k = blockIdx.x * 256 + threadIdx.x;
    int t0 = seg * 256;
    sw[threadIdx.x] = g_w[b * SRC + t0 + threadIdx.x];
    __syncthreads();
    const float* ep = enc + ((size_t)b * SRC + t0) * ENCD + k;
    float a0 = 0.f, a1 = 0.f, a2 = 0.f, a3 = 0.f;
#pragma unroll 4
    for (int t = 0; t < 256; t += 4) {
        a0 += sw[t] * ep[(size_t)t * ENCD];
        a1 += sw[t + 1] * ep[(size_t)(t + 1) * ENCD];
        a2 += sw[t + 2] * ep[(size_t)(t + 2) * ENCD];
        a3 += sw[t + 3] * ep[(size_t)(t + 3) * ENCD];
    }
    g_ctxp[seg][b][k] = (a0 + a1) + (a2 + a3);
}

__global__ void k_ctx_red() {
    int i = blockIdx.x * 256 + threadIdx.x;
    const float* p = &g_ctxp[0][0][0];
    float s = 0.f;
#pragma unroll
    for (int seg = 0; seg < 8; seg++) s += p[seg * BB * ENCD + i];
    g_ctx[i] = s;
}

// ---------------- k_xin -------------------------------------------------------
__global__ void k_xin(const int* __restrict__ x, const float* __restrict__ emb) {
    int b = blockIdx.x;
    int xi = x[b];
    for (int i = threadIdx.x; i < IN0; i += 256) {
        float v = (i < ENCD) ? g_ctx[b * ENCD + i]
                             : emb[(size_t)xi * EE + (i - ENCD)];
        g_xin[b * IN0 + i] = v;
    }
}

// ---------------- legacy tf32 GEMM body: C(64xN) = A(64xK)@B(KxN) [+bias] ---
template <int EPI>
__device__ __forceinline__ void gemm_body(const float* __restrict__ A,
                                          const float* __restrict__ B,
                                          const float* __restrict__ bias,
                                          float* __restrict__ C, int K, int N,
                                          int col0) {
    __shared__ __align__(16) unsigned sA[64 * 36];
    __shared__ __align__(16) unsigned sB[32 * 132];
    const int tid = threadIdx.x;
    const int wid = tid >> 5, lane = tid & 31;
    const int wm = wid & 1, wn = wid >> 1;
    const int g = lane >> 2, tg = lane & 3;

    float c[2][4][4];
#pragma unroll
    for (int a = 0; a < 2; a++)
#pragma unroll
        for (int b2 = 0; b2 < 4; b2++)
#pragma unroll
            for (int d = 0; d < 4; d++) c[a][b2][d] = 0.f;

    for (int k0 = 0; k0 < K; k0 += 32) {
#pragma unroll
        for (int i = 0; i < 2; i++) {
            int idx = tid + i * 256;
            int row = idx >> 3, c4 = idx & 7;
            float4 v = *reinterpret_cast<const float4*>(A + (size_t)row * K + k0 + c4 * 4);
            *reinterpret_cast<uint4*>(&sA[row * 36 + c4 * 4]) = cvt4(v);
        }
#pragma unroll
        for (int i = 0; i < 4; i++) {
            int idx = tid + i * 256;
            int rb = idx >> 5, c4 = idx & 31;
            float4 v = *reinterpret_cast<const float4*>(B + (size_t)(k0 + rb) * N + col0 + c4 * 4);
            *reinterpret_cast<uint4*>(&sB[rb * 132 + c4 * 4]) = cvt4(v);
        }
        __syncthreads();
#pragma unroll
        for (int ks = 0; ks < 4; ks++) {
            const int kb = ks * 8;
            unsigned af[2][4], bf[4][2];
#pragma unroll
            for (int mt = 0; mt < 2; mt++) {
                int r = wm * 32 + mt * 16 + g;
                af[mt][0] = sA[r * 36 + kb + tg];
                af[mt][1] = sA[(r + 8) * 36 + kb + tg];
                af[mt][2] = sA[r * 36 + kb + tg + 4];
                af[mt][3] = sA[(r + 8) * 36 + kb + tg + 4];
            }
#pragma unroll
            for (int nt = 0; nt < 4; nt++) {
                int col = wn * 32 + nt * 8 + g;
                bf[nt][0] = sB[(kb + tg) * 132 + col];
                bf[nt][1] = sB[(kb + tg + 4) * 132 + col];
            }
#pragma unroll
            for (int mt = 0; mt < 2; mt++)
#pragma unroll
                for (int nt = 0; nt < 4; nt++) MMA_TF32(c[mt][nt], af[mt], bf[nt]);
        }
        __syncthreads();
    }
#pragma unroll
    for (int mt = 0; mt < 2; mt++)
#pragma unroll
        for (int nt = 0; nt < 4; nt++) {
            int r = wm * 32 + mt * 16 + g;
            int col = col0 + wn * 32 + nt * 8 + tg * 2;
            float add0 = 0.f, add1 = 0.f;
            if (EPI == 1) { add0 = bias[col]; add1 = bias[col + 1]; }
            C[(size_t)r * N + col] = c[mt][nt][0] + add0;
            C[(size_t)r * N + col + 1] = c[mt][nt][1] + add1;
            C[(size_t)(r + 8) * N + col] = c[mt][nt][2] + add0;
            C[(size_t)(r + 8) * N + col + 1] = c[mt][nt][3] + add1;
        }
}

template <int EPI>
__global__ __launch_bounds__(256, 2) void k_gemm(const float* __restrict__ A,
                                                 const float* __restrict__ B,
                                                 const float* __restrict__ bias,
                                                 float* __restrict__ C, int K, int N) {
    gemm_body<EPI>(A, B, bias, C, K, N, blockIdx.x * 128);
}

__global__ __launch_bounds__(256, 2) void k_gemm_pair(
    const float* A0, const float* A1, const float* B0, const float* B1,
    float* C0, float* C1, int K, int N) {
    const float* A = blockIdx.y ? A1 : A0;
    const float* B = blockIdx.y ? B1 : B0;
    float* C = blockIdx.y ? C1 : C0;
    gemm_body<0>(A, B, nullptr, C, K, N, blockIdx.x * 128);
}

// ---------------- k_gru_pair : pointwise GRU, zero hidden state -------------
__global__ void k_gru_pair(const float* xg0, const float* xg1,
                           const float* b0v, const float* b1v,
                           float* o0, float* o1) {
    const float* xg = blockIdx.y ? xg1 : xg0;
    const float* bvec = blockIdx.y ? b1v : b0v;
    float* hout = blockIdx.y ? o1 : o0;
    int b = blockIdx.x;
    for (int u = threadIdx.x; u < UU; u += 256) {
        float xz = xg[b * 3 * UU + u] + bvec[u] + bvec[3 * UU + u];
        float xr = xg[b * 3 * UU + UU + u] + bvec[UU + u] + bvec[3 * UU + UU + u];
        float xh = xg[b * 3 * UU + 2 * UU + u] + bvec[2 * UU + u];
        float b1h = bvec[3 * UU + 2 * UU + u];
        float z = 1.f / (1.f + expf(-xz));
        float r = 1.f / (1.f + expf(-xr));
        float hc = tanhf(xh + r * b1h);
        hout[b * UU + u] = (1.f - z) * hc;
    }
}

// ---------------- k_concat ----------------------------------------------------
__global__ void k_concat(const float* __restrict__ h1f, const float* __restrict__ h1b) {
    int b = blockIdx.x;
    for (int i = threadIdx.x; i < 2 * UU; i += 256)
        g_y[b * 2 * UU + i] = (i < UU) ? h1f[b * UU + i] : h1b[b * UU + i - UU];
}

// ---------------- host launcher ----------------------------------------------
extern "C" void kernel_launch(void* const* d_in, const int* in_sizes, int n_in,
                              void* d_out, int out_size) {
    (void)in_sizes; (void)n_in; (void)out_size;
    const int* x = (const int*)d_in[0];
    const float* state = (const float*)d_in[1];
    const float* enc = (const float*)d_in[2];
    const float* Wh = (const float*)d_in[3];
    const float* bh = (const float*)d_in[4];
    const float* Wc = (const float*)d_in[5];
    const float* bc = (const float*)d_in[6];
    const float* Ws = (const float*)d_in[7];
    const float* bs = (const float*)d_in[8];
    const float* emb = (const float*)d_in[9];
    const float* fw0_k = (const float*)d_in[10];
    const float* fw0_b = (const float*)d_in[12];
    const float* fw1_k = (const float*)d_in[13];
    const float* fw1_b = (const float*)d_in[15];
    const float* bw0_k = (const float*)d_in[16];
    const float* bw0_b = (const float*)d_in[18];
    const float* bw1_k = (const float*)d_in[19];
    const float* bw1_b = (const float*)d_in[21];
    const float* fcW = (const float*)d_in[22];
    const float* fcb = (const float*)d_in[23];

    float* out = (float*)d_out;
    float* h0f = out + (size_t)BB * VV;
    float* h1f = h0f + BB * UU;
    float* h0b = h1f + BB * UU;
    float* h1b = h0b + BB * UU;

    float *p_xin, *p_xg0, *p_xg1, *p_y;
    cudaGetSymbolAddress((void**)&p_xin, g_xin);
    cudaGetSymbolAddress((void**)&p_xg0, g_xg);
    p_xg1 = p_xg0 + BB * 3 * UU;
    cudaGetSymbolAddress((void**)&p_y, g_y);

    cudaFuncSetAttribute(k_score, cudaFuncAttributeMaxDynamicSharedMemorySize, SC_SMEM);

    // attention
    k_enc2h<<<(size_t)MROWS * ENCD / (256 * 8), 256>>>(enc);
    k_transpose<<<dim3(32, 32), dim3(32, 8)>>>(Wc);
    k_h<<<BB, 256>>>(state, Wh, bh);
    k_score<<<MROWS / 128, 256, SC_SMEM>>>(bc, Ws);
    k_softmax<<<BB, 256>>>(bs);
    k_ctx<<<dim3(ENCD / 256, BB, 8), 256>>>(enc);
    k_ctx_red<<<BB * ENCD / 256, 256>>>();
    k_xin<<<BB, 256>>>(x, emb);

    // GRU stacks (zero hidden state => rk unused); fw/bw paired
    k_gemm_pair<<<dim3(3 * UU / 128, 2), 256>>>(p_xin, p_xin, fw0_k, bw0_k,
                                                p_xg0, p_xg1, IN0, 3 * UU);
    k_gru_pair<<<dim3(BB, 2), 256>>>(p_xg0, p_xg1, fw0_b, bw0_b, h0f, h0b);
    k_gemm_pair<<<dim3(3 * UU / 128, 2), 256>>>(h0f, h0b, fw1_k, bw1_k,
                                                p_xg0, p_xg1, UU, 3 * UU);
    k_gru_pair<<<dim3(BB, 2), 256>>>(p_xg0, p_xg1, fw1_b, bw1_b, h1f, h1b);

    // output projection
    k_concat<<<BB, 256>>>(h1f, h1b);
    k_gemm<1><<<dim3(VV / 128, 1), 256>>>(p_y, fcW, fcb, out, 2 * UU, VV);
}

// round 5
// speedup vs baseline: 1.9587x; 1.1295x over previous
#include <cuda_runtime.h>
#include <cuda_fp16.h>
#include <cstdint>

// Problem constants
#define BB   64
#define SRC  2048
#define ENCD 1024
#define UU   1024
#define EE   512
#define VV   32000
#define IN0  (ENCD + EE)        // 1536
#define MROWS (BB * SRC)        // 131072

// ---------------- scratch (device globals; no allocation allowed) -----------
__device__ float  g_h[BB * UU];
__device__ __half g_encH[(size_t)MROWS * ENCD];   // enc in fp16 (256MB)
__device__ __half g_WcTH[ENCD * UU];              // Wc transposed fp16
__device__ float  g_s[MROWS];                     // scores
__device__ float  g_w[BB * SRC];
__device__ float  g_ctxp[8][BB][ENCD];
__device__ float  g_xin[BB * IN0];
__device__ float  g_xg[2][BB * 3 * UU];
__device__ float  g_y[BB * 2 * UU];

// ---------------- helpers ----------------------------------------------------
__device__ __forceinline__ unsigned f2tf32(float f) {
    unsigned u;
    asm("cvt.rna.tf32.f32 %0, %1;" : "=r"(u) : "f"(f));
    return u;
}
__device__ __forceinline__ uint4 cvt4(float4 v) {
    uint4 u;
    u.x = f2tf32(v.x); u.y = f2tf32(v.y); u.z = f2tf32(v.z); u.w = f2tf32(v.w);
    return u;
}
__device__ __forceinline__ float htanh(float x) {
    float r;
    asm("tanh.approx.f32 %0, %1;" : "=f"(r) : "f"(x));
    return r;
}
__device__ __forceinline__ uint32_t smem_u32(const void* p) {
    uint32_t a;
    asm("{ .reg .u64 t; cvta.to.shared.u64 t, %1; cvt.u32.u64 %0, t; }" : "=r"(a) : "l"(p));
    return a;
}
__device__ __forceinline__ void cp16(uint32_t dst, const void* src) {
    asm volatile("cp.async.cg.shared.global [%0], [%1], 16;\n" :: "r"(dst), "l"(src));
}
#define CP_COMMIT() asm volatile("cp.async.commit_group;" ::: "memory")
#define CP_WAIT0()  asm volatile("cp.async.wait_group 0;" ::: "memory")

#define LDSM4(r0, r1, r2, r3, addr)                                              \
    asm volatile("ldmatrix.sync.aligned.m8n8.x4.shared.b16 {%0,%1,%2,%3}, [%4];" \
                 : "=r"(r0), "=r"(r1), "=r"(r2), "=r"(r3) : "r"(addr))

// fp16 mma m16n8k16 with fp32 accumulate
#define MMA_F16(c, a, b)                                                         \
    asm volatile(                                                                \
        "mma.sync.aligned.m16n8k16.row.col.f32.f16.f16.f32 "                     \
        "{%0,%1,%2,%3},{%4,%5,%6,%7},{%8,%9},{%0,%1,%2,%3};\n"                   \
        : "+f"((c)[0]), "+f"((c)[1]), "+f"((c)[2]), "+f"((c)[3])                 \
        : "r"((a)[0]), "r"((a)[1]), "r"((a)[2]), "r"((a)[3]),                    \
          "r"((b)[0]), "r"((b)[1]))

// tf32 mma m16n8k8 (small GEMMs)
#define MMA_TF32(c, a, b)                                                        \
    asm volatile(                                                                \
        "mma.sync.aligned.m16n8k8.row.col.f32.tf32.tf32.f32 "                    \
        "{%0,%1,%2,%3},{%4,%5,%6,%7},{%8,%9},{%0,%1,%2,%3};\n"                   \
        : "+f"((c)[0]), "+f"((c)[1]), "+f"((c)[2]), "+f"((c)[3])                 \
        : "r"((a)[0]), "r"((a)[1]), "r"((a)[2]), "r"((a)[3]),                    \
          "r"((b)[0]), "r"((b)[1]))

// ---------------- k_prep : fused enc->fp16 | Wc transpose | h = state@Wh+bh --
#define PREP_ENC_BLKS 65536          // MROWS*ENCD / (256*8)
#define PREP_TR_BLKS  1024           // 32x32 tiles of Wc
#define PREP_TOTAL (PREP_ENC_BLKS + PREP_TR_BLKS + BB)

__global__ void k_prep(const float* __restrict__ enc, const float* __restrict__ Wc,
                       const float* __restrict__ state, const float* __restrict__ Wh,
                       const float* __restrict__ bh) {
    __shared__ float sbuf[32 * 33];
    const int bx = blockIdx.x, tid = threadIdx.x;

    if (bx < PREP_ENC_BLKS) {
        size_t i = ((size_t)bx * 256 + tid) * 8;
        float4 v0 = *reinterpret_cast<const float4*>(enc + i);
        float4 v1 = *reinterpret_cast<const float4*>(enc + i + 4);
        __half2 h[4];
        h[0] = __floats2half2_rn(v0.x, v0.y);
        h[1] = __floats2half2_rn(v0.z, v0.w);
        h[2] = __floats2half2_rn(v1.x, v1.y);
        h[3] = __floats2half2_rn(v1.z, v1.w);
        *reinterpret_cast<uint4*>(&g_encH[i]) = *reinterpret_cast<uint4*>(h);
    } else if (bx < PREP_ENC_BLKS + PREP_TR_BLKS) {
        int t2 = bx - PREP_ENC_BLKS;
        int j0 = (t2 & 31) * 32, k0 = (t2 >> 5) * 32;
        int lx = tid & 31, ly = tid >> 5;   // lx: 0..31, ly: 0..7
        float (*t)[33] = reinterpret_cast<float(*)[33]>(sbuf);
#pragma unroll
        for (int i = 0; i < 4; i++) {
            int kk = ly + i * 8;
            t[kk][lx] = Wc[(size_t)(k0 + kk) * UU + j0 + lx];
        }
        __syncthreads();
#pragma unroll
        for (int i = 0; i < 4; i++) {
            int jj = ly + i * 8;
            g_WcTH[(size_t)(j0 + jj) * ENCD + k0 + lx] = __float2half_rn(t[lx][jj]);
        }
    } else {
        int b = bx - PREP_ENC_BLKS - PREP_TR_BLKS;
        float* ss = sbuf;
        for (int i = tid; i < UU; i += 256) ss[i] = state[b * UU + i];
        __syncthreads();
        float acc[4] = {0.f, 0.f, 0.f, 0.f};
#pragma unroll 4
        for (int k = 0; k < UU; k++) {
            float sv = ss[k];
            const float* wr = Wh + (size_t)k * UU + tid;
            acc[0] += sv * wr[0];
            acc[1] += sv * wr[256];
            acc[2] += sv * wr[512];
            acc[3] += sv * wr[768];
        }
#pragma unroll
        for (int jj = 0; jj < 4; jj++) {
            int j = tid + jj * 256;
            g_h[b * UU + j] = acc[jj] + bh[j];
        }
    }
}

// ---------------- k_score : fp16 mma, BK=64, 2-stage single-sync pipeline ---
// one CTA per 128-row block; 8 j-tiles x 16 k-chunks = 128 pipeline iterations
#define SKW 36                   // smem row stride in words (32 data + 4 pad)
#define NST 2
#define STGW (128 * SKW)         // words per stage per array
#define STGB (STGW * 4)          // bytes per stage per array (18432)
#define SC_SMEM (2 * NST * STGB + 3 * 128 * 4)

__global__ __launch_bounds__(256, 2) void k_score(const float* __restrict__ bc,
                                                  const float* __restrict__ Ws) {
    extern __shared__ char dsm[];
    uint32_t* sAp = reinterpret_cast<uint32_t*>(dsm);
    uint32_t* sBp = sAp + NST * STGW;
    float* shb = reinterpret_cast<float*>(sBp + NST * STGW);
    float* sws = shb + 128;
    float* srow = sws + 128;

    const int tid = threadIdx.x, wid = tid >> 5, lane = tid & 31;
    const int wm = wid & 1, wn = wid >> 1;
    const int g = lane >> 2, tg = lane & 3;
    const int R0 = blockIdx.x * 128;
    const int bidx = blockIdx.x >> 4;      // 2048 rows per batch element

    if (tid < 128) srow[tid] = 0.f;

    const uint32_t sA0 = smem_u32(sAp);
    const uint32_t sB0 = smem_u32(sBp);
    const __half* aBase = g_encH + (size_t)R0 * ENCD;

    // ldmatrix per-lane byte offsets within a stage (ks adds ks*32 bytes)
    uint32_t aOff[4], bOff[2];
#pragma unroll
    for (int mt = 0; mt < 4; mt++) {
        int row = wm * 64 + mt * 16 + ((lane >> 3) & 1) * 8 + (lane & 7);
        aOff[mt] = (row * SKW + ((lane >> 4) << 2)) * 4;
    }
#pragma unroll
    for (int np = 0; np < 2; np++) {
        int row = wn * 32 + np * 16 + ((lane >> 4) & 1) * 8 + (lane & 7);
        bOff[np] = (row * SKW + (((lane >> 3) & 1) << 2)) * 4;
    }

    // stage loader for pipeline iteration 'it' (BK=64 halves per row)
    auto load_it = [&](int it) {
        int kc = it & 15, jt = it >> 4, s = it & 1;
        const __half* aSrc = aBase + kc * 64;
        const __half* bSrc = g_WcTH + (size_t)(jt * 128) * ENCD + kc * 64;
        uint32_t aDst = sA0 + s * STGB;
        uint32_t bDst = sB0 + s * STGB;
#pragma unroll
        for (int i = 0; i < 4; i++) {
            int idx = tid + i * 256;        // 0..1023
            int row = idx >> 3, seg = idx & 7;
            cp16(aDst + (row * SKW + seg * 4) * 4, aSrc + (size_t)row * ENCD + seg * 8);
            cp16(bDst + (row * SKW + seg * 4) * 4, bSrc + (size_t)row * ENCD + seg * 8);
        }
    };

    float c[4][4][4];
#pragma unroll
    for (int a = 0; a < 4; a++)
#pragma unroll
        for (int b2 = 0; b2 < 4; b2++)
#pragma unroll
            for (int d = 0; d < 4; d++) c[a][b2][d] = 0.f;
    float rowacc[4][2] = {{0.f, 0.f}, {0.f, 0.f}, {0.f, 0.f}, {0.f, 0.f}};

    load_it(0); CP_COMMIT();

    const int TOT = 128;
    for (int it = 0; it < TOT; it++) {
        const int kc = it & 15, jt = it >> 4, s = it & 1;
        CP_WAIT0();
        __syncthreads();          // stage 'it' visible; stage s^1 free (compute it-1 done)

        if (kc == 0 && tid < 128) {
            int j = jt * 128 + tid;
            shb[tid] = g_h[bidx * UU + j] + bc[j];
            sws[tid] = Ws[j];
        }

        if (it + 1 < TOT) load_it(it + 1);
        CP_COMMIT();

        const uint32_t aB = sA0 + s * STGB;
        const uint32_t bB = sB0 + s * STGB;
#pragma unroll
        for (int ks = 0; ks < 4; ks++) {
            uint32_t bf[4][2];
#pragma unroll
            for (int np = 0; np < 2; np++)
                LDSM4(bf[2 * np][0], bf[2 * np][1], bf[2 * np + 1][0], bf[2 * np + 1][1],
                      bB + bOff[np] + ks * 32);
#pragma unroll
            for (int mt = 0; mt < 4; mt++) {
                uint32_t af[4];
                LDSM4(af[0], af[1], af[2], af[3], aB + aOff[mt] + ks * 32);
#pragma unroll
                for (int nt = 0; nt < 4; nt++) MMA_F16(c[mt][nt], af, bf[nt]);
            }
        }

        if (kc == 15) {
            // epilogue for this j-tile: accumulate tanh(c + hb) * ws per row
#pragma unroll
            for (int mt = 0; mt < 4; mt++) {
                float rs0 = 0.f, rs1 = 0.f;
#pragma unroll
                for (int nt = 0; nt < 4; nt++) {
                    int nl = wn * 32 + nt * 8 + tg * 2;
#pragma unroll
                    for (int cc = 0; cc < 2; cc++) {
                        float hb = shb[nl + cc], ws = sws[nl + cc];
                        rs0 += htanh(c[mt][nt][cc] + hb) * ws;
                        rs1 += htanh(c[mt][nt][2 + cc] + hb) * ws;
                    }
                }
                rs0 += __shfl_xor_sync(0xffffffffu, rs0, 1);
                rs0 += __shfl_xor_sync(0xffffffffu, rs0, 2);
                rs1 += __shfl_xor_sync(0xffffffffu, rs1, 1);
                rs1 += __shfl_xor_sync(0xffffffffu, rs1, 2);
                rowacc[mt][0] += rs0;
                rowacc[mt][1] += rs1;
#pragma unroll
                for (int nt = 0; nt < 4; nt++)
#pragma unroll
                    for (int d = 0; d < 4; d++) c[mt][nt][d] = 0.f;
            }
        }
    }

    // cross-warp (wn) reduction via smem atomics
#pragma unroll
    for (int mt = 0; mt < 4; mt++) {
        if (tg == 0) {
            atomicAdd(&srow[wm * 64 + mt * 16 + g], rowacc[mt][0]);
            atomicAdd(&srow[wm * 64 + mt * 16 + 8 + g], rowacc[mt][1]);
        }
    }
    __syncthreads();
    if (tid < 128) g_s[R0 + tid] = srow[tid];
}

// ---------------- k_softmax ---------------------------------------------------
__global__ void k_softmax(const float* __restrict__ bs) {
    __shared__ float sv[SRC];
    __shared__ float red[256];
    int b = blockIdx.x, tid = threadIdx.x;
    float bsv = bs[0];
    float lmax = -1e30f;
    for (int t = tid; t < SRC; t += 256) {
        float s = bsv + g_s[b * SRC + t];
        sv[t] = s;
        lmax = fmaxf(lmax, s);
    }
    red[tid] = lmax;
    __syncthreads();
    for (int off = 128; off; off >>= 1) {
        if (tid < off) red[tid] = fmaxf(red[tid], red[tid + off]);
        __syncthreads();
    }
    float m = red[0];
    __syncthreads();
    float lsum = 0.f;
    for (int t = tid; t < SRC; t += 256) {
        float e = expf(sv[t] - m);
        sv[t] = e;
        lsum += e;
    }
    red[tid] = lsum;
    __syncthreads();
    for (int off = 128; off; off >>= 1) {
        if (tid < off) red[tid] += red[tid + off];
        __syncthreads();
    }
    float inv = 1.f / red[0];
    for (int t = tid; t < SRC; t += 256) g_w[b * SRC + t] = sv[t] * inv;
}

// ---------------- k_ctx : segmented weighted sum over fp16 enc ---------------
__global__ void k_ctx() {
    __shared__ float sw[256];
    int b = blockIdx.y, seg = blockIdx.z;
    int k = blockIdx.x * 256 + threadIdx.x;
    int t0 = seg * 256;
    sw[threadIdx.x] = g_w[b * SRC + t0 + threadIdx.x];
    __syncthreads();
    const __half* ep = g_encH + ((size_t)b * SRC + t0) * ENCD + k;
    float a0 = 0.f, a1 = 0.f, a2 = 0.f, a3 = 0.f;
#pragma unroll 4
    for (int t = 0; t < 256; t += 4) {
        a0 += sw[t] * __half2float(ep[(size_t)t * ENCD]);
        a1 += sw[t + 1] * __half2float(ep[(size_t)(t + 1) * ENCD]);
        a2 += sw[t + 2] * __half2float(ep[(size_t)(t + 2) * ENCD]);
        a3 += sw[t + 3] * __half2float(ep[(size_t)(t + 3) * ENCD]);
    }
    g_ctxp[seg][b][k] = (a0 + a1) + (a2 + a3);
}

// ---------------- k_xin : xin = concat(sum(ctx partials), emb[x]) ------------
__global__ void k_xin(const int* __restrict__ x, const float* __restrict__ emb) {
    int b = blockIdx.x;
    int xi = x[b];
    for (int i = threadIdx.x; i < IN0; i += 256) {
        float v;
        if (i < ENCD) {
            v = 0.f;
#pragma unroll
            for (int seg = 0; seg < 8; seg++) v += g_ctxp[seg][b][i];
        } else {
            v = emb[(size_t)xi * EE + (i - ENCD)];
        }
        g_xin[b * IN0 + i] = v;
    }
}

// ---------------- legacy tf32 GEMM body: C(64xN) = A(64xK)@B(KxN) [+bias] ---
template <int EPI>
__device__ __forceinline__ void gemm_body(const float* __restrict__ A,
                                          const float* __restrict__ B,
                                          const float* __restrict__ bias,
                                          float* __restrict__ C, int K, int N,
                                          int col0) {
    __shared__ __align__(16) unsigned sA[64 * 36];
    __shared__ __align__(16) unsigned sB[32 * 132];
    const int tid = threadIdx.x;
    const int wid = tid >> 5, lane = tid & 31;
    const int wm = wid & 1, wn = wid >> 1;
    const int g = lane >> 2, tg = lane & 3;

    float c[2][4][4];
#pragma unroll
    for (int a = 0; a < 2; a++)
#pragma unroll
        for (int b2 = 0; b2 < 4; b2++)
#pragma unroll
            for (int d = 0; d < 4; d++) c[a][b2][d] = 0.f;

    for (int k0 = 0; k0 < K; k0 += 32) {
#pragma unroll
        for (int i = 0; i < 2; i++) {
            int idx = tid + i * 256;
            int row = idx >> 3, c4 = idx & 7;
            float4 v = *reinterpret_cast<const float4*>(A + (size_t)row * K + k0 + c4 * 4);
            *reinterpret_cast<uint4*>(&sA[row * 36 + c4 * 4]) = cvt4(v);
        }
#pragma unroll
        for (int i = 0; i < 4; i++) {
            int idx = tid + i * 256;
            int rb = idx >> 5, c4 = idx & 31;
            float4 v = *reinterpret_cast<const float4*>(B + (size_t)(k0 + rb) * N + col0 + c4 * 4);
            *reinterpret_cast<uint4*>(&sB[rb * 132 + c4 * 4]) = cvt4(v);
        }
        __syncthreads();
#pragma unroll
        for (int ks = 0; ks < 4; ks++) {
            const int kb = ks * 8;
            unsigned af[2][4], bf[4][2];
#pragma unroll
            for (int mt = 0; mt < 2; mt++) {
                int r = wm * 32 + mt * 16 + g;
                af[mt][0] = sA[r * 36 + kb + tg];
                af[mt][1] = sA[(r + 8) * 36 + kb + tg];
                af[mt][2] = sA[r * 36 + kb + tg + 4];
                af[mt][3] = sA[(r + 8) * 36 + kb + tg + 4];
            }
#pragma unroll
            for (int nt = 0; nt < 4; nt++) {
                int col = wn * 32 + nt * 8 + g;
                bf[nt][0] = sB[(kb + tg) * 132 + col];
                bf[nt][1] = sB[(kb + tg + 4) * 132 + col];
            }
#pragma unroll
            for (int mt = 0; mt < 2; mt++)
#pragma unroll
                for (int nt = 0; nt < 4; nt++) MMA_TF32(c[mt][nt], af[mt], bf[nt]);
        }
        __syncthreads();
    }
#pragma unroll
    for (int mt = 0; mt < 2; mt++)
#pragma unroll
        for (int nt = 0; nt < 4; nt++) {
            int r = wm * 32 + mt * 16 + g;
            int col = col0 + wn * 32 + nt * 8 + tg * 2;
            float add0 = 0.f, add1 = 0.f;
            if (EPI == 1) { add0 = bias[col]; add1 = bias[col + 1]; }
            C[(size_t)r * N + col] = c[mt][nt][0] + add0;
            C[(size_t)r * N + col + 1] = c[mt][nt][1] + add1;
            C[(size_t)(r + 8) * N + col] = c[mt][nt][2] + add0;
            C[(size_t)(r + 8) * N + col + 1] = c[mt][nt][3] + add1;
        }
}

template <int EPI>
__global__ __launch_bounds__(256, 2) void k_gemm(const float* __restrict__ A,
                                                 const float* __restrict__ B,
                                                 const float* __restrict__ bias,
                                                 float* __restrict__ C, int K, int N) {
    gemm_body<EPI>(A, B, bias, C, K, N, blockIdx.x * 128);
}

__global__ __launch_bounds__(256, 2) void k_gemm_pair(
    const float* A0, const float* A1, const float* B0, const float* B1,
    float* C0, float* C1, int K, int N) {
    const float* A = blockIdx.y ? A1 : A0;
    const float* B = blockIdx.y ? B1 : B0;
    float* C = blockIdx.y ? C1 : C0;
    gemm_body<0>(A, B, nullptr, C, K, N, blockIdx.x * 128);
}

// ---------------- k_gru_pair : pointwise GRU, zero hidden state -------------
__global__ void k_gru_pair(const float* xg0, const float* xg1,
                           const float* b0v, const float* b1v,
                           float* o0, float* o1) {
    const float* xg = blockIdx.y ? xg1 : xg0;
    const float* bvec = blockIdx.y ? b1v : b0v;
    float* hout = blockIdx.y ? o1 : o0;
    int b = blockIdx.x;
    for (int u = threadIdx.x; u < UU; u += 256) {
        float xz = xg[b * 3 * UU + u] + bvec[u] + bvec[3 * UU + u];
        float xr = xg[b * 3 * UU + UU + u] + bvec[UU + u] + bvec[3 * UU + UU + u];
        float xh = xg[b * 3 * UU + 2 * UU + u] + bvec[2 * UU + u];
        float b1h = bvec[3 * UU + 2 * UU + u];
        float z = 1.f / (1.f + expf(-xz));
        float r = 1.f / (1.f + expf(-xr));
        float hc = tanhf(xh + r * b1h);
        hout[b * UU + u] = (1.f - z) * hc;
    }
}

// ---------------- k_concat ----------------------------------------------------
__global__ void k_concat(const float* __restrict__ h1f, const float* __restrict__ h1b) {
    int b = blockIdx.x;
    for (int i = threadIdx.x; i < 2 * UU; i += 256)
        g_y[b * 2 * UU + i] = (i < UU) ? h1f[b * UU + i] : h1b[b * UU + i - UU];
}

// ---------------- host launcher ----------------------------------------------
extern "C" void kernel_launch(void* const* d_in, const int* in_sizes, int n_in,
                              void* d_out, int out_size) {
    (void)in_sizes; (void)n_in; (void)out_size;
    const int* x = (const int*)d_in[0];
    const float* state = (const float*)d_in[1];
    const float* enc = (const float*)d_in[2];
    const float* Wh = (const float*)d_in[3];
    const float* bh = (const float*)d_in[4];
    const float* Wc = (const float*)d_in[5];
    const float* bc = (const float*)d_in[6];
    const float* Ws = (const float*)d_in[7];
    const float* bs = (const float*)d_in[8];
    const float* emb = (const float*)d_in[9];
    const float* fw0_k = (const float*)d_in[10];
    const float* fw0_b = (const float*)d_in[12];
    const float* fw1_k = (const float*)d_in[13];
    const float* fw1_b = (const float*)d_in[15];
    const float* bw0_k = (const float*)d_in[16];
    const float* bw0_b = (const float*)d_in[18];
    const float* bw1_k = (const float*)d_in[19];
    const float* bw1_b = (const float*)d_in[21];
    const float* fcW = (const float*)d_in[22];
    const float* fcb = (const float*)d_in[23];

    float* out = (float*)d_out;
    float* h0f = out + (size_t)BB * VV;
    float* h1f = h0f + BB * UU;
    float* h0b = h1f + BB * UU;
    float* h1b = h0b + BB * UU;

    float *p_xin, *p_xg0, *p_xg1, *p_y;
    cudaGetSymbolAddress((void**)&p_xin, g_xin);
    cudaGetSymbolAddress((void**)&p_xg0, g_xg);
    p_xg1 = p_xg0 + BB * 3 * UU;
    cudaGetSymbolAddress((void**)&p_y, g_y);

    cudaFuncSetAttribute(k_score, cudaFuncAttributeMaxDynamicSharedMemorySize, SC_SMEM);

    // attention
    k_prep<<<PREP_TOTAL, 256>>>(enc, Wc, state, Wh, bh);
    k_score<<<MROWS / 128, 256, SC_SMEM>>>(bc, Ws);
    k_softmax<<<BB, 256>>>(bs);
    k_ctx<<<dim3(ENCD / 256, BB, 8), 256>>>();
    k_xin<<<BB, 256>>>(x, emb);

    // GRU stacks (zero hidden state => rk unused); fw/bw paired
    k_gemm_pair<<<dim3(3 * UU / 128, 2), 256>>>(p_xin, p_xin, fw0_k, bw0_k,
                                                p_xg0, p_xg1, IN0, 3 * UU);
    k_gru_pair<<<dim3(BB, 2), 256>>>(p_xg0, p_xg1, fw0_b, bw0_b, h0f, h0b);
    k_gemm_pair<<<dim3(3 * UU / 128, 2), 256>>>(h0f, h0b, fw1_k, bw1_k,
                                                p_xg0, p_xg1, UU, 3 * UU);
    k_gru_pair<<<dim3(BB, 2), 256>>>(p_xg0, p_xg1, fw1_b, bw1_b, h1f, h1b);

    // output projection
    k_concat<<<BB, 256>>>(h1f, h1b);
    k_gemm<1><<<dim3(VV / 128, 1), 256>>>(p_y, fcW, fcb, out, 2 * UU, VV);
}

// round 6
// speedup vs baseline: 2.1457x; 1.0955x over previous
#include <cuda_runtime.h>
#include <cuda_fp16.h>
#include <cstdint>

// Problem constants
#define BB   64
#define SRC  2048
#define ENCD 1024
#define UU   1024
#define EE   512
#define VV   32000
#define IN0  (ENCD + EE)        // 1536
#define MROWS (BB * SRC)        // 131072
#define XSEG (BB * 3 * UU)      // one gate-preact buffer

// ---------------- scratch (device globals; no allocation allowed) -----------
__device__ float  g_h[BB * UU];
__device__ __half g_encH[(size_t)MROWS * ENCD];   // enc in fp16 (256MB)
__device__ __half g_WcTH[ENCD * UU];              // Wc transposed fp16
__device__ float  g_s[MROWS];                     // scores
__device__ float  g_w[BB * SRC];
__device__ float  g_ctxp[8][BB][ENCD];
__device__ float  g_xin[BB * IN0];
__device__ float  g_xgp[4][2][XSEG];              // split-K partials
__device__ float  g_y[BB * 2 * UU];

// ---------------- helpers ----------------------------------------------------
__device__ __forceinline__ unsigned f2tf32(float f) {
    unsigned u;
    asm("cvt.rna.tf32.f32 %0, %1;" : "=r"(u) : "f"(f));
    return u;
}
__device__ __forceinline__ uint4 cvt4(float4 v) {
    uint4 u;
    u.x = f2tf32(v.x); u.y = f2tf32(v.y); u.z = f2tf32(v.z); u.w = f2tf32(v.w);
    return u;
}
__device__ __forceinline__ float htanh(float x) {
    float r;
    asm("tanh.approx.f32 %0, %1;" : "=f"(r) : "f"(x));
    return r;
}
__device__ __forceinline__ uint32_t smem_u32(const void* p) {
    uint32_t a;
    asm("{ .reg .u64 t; cvta.to.shared.u64 t, %1; cvt.u32.u64 %0, t; }" : "=r"(a) : "l"(p));
    return a;
}
__device__ __forceinline__ void cp16(uint32_t dst, const void* src) {
    asm volatile("cp.async.cg.shared.global [%0], [%1], 16;\n" :: "r"(dst), "l"(src));
}
#define CP_COMMIT() asm volatile("cp.async.commit_group;" ::: "memory")
#define CP_WAIT0()  asm volatile("cp.async.wait_group 0;" ::: "memory")

#define LDSM4(r0, r1, r2, r3, addr)                                              \
    asm volatile("ldmatrix.sync.aligned.m8n8.x4.shared.b16 {%0,%1,%2,%3}, [%4];" \
                 : "=r"(r0), "=r"(r1), "=r"(r2), "=r"(r3) : "r"(addr))

// fp16 mma m16n8k16 with fp32 accumulate
#define MMA_F16(c, a, b)                                                         \
    asm volatile(                                                                \
        "mma.sync.aligned.m16n8k16.row.col.f32.f16.f16.f32 "                     \
        "{%0,%1,%2,%3},{%4,%5,%6,%7},{%8,%9},{%0,%1,%2,%3};\n"                   \
        : "+f"((c)[0]), "+f"((c)[1]), "+f"((c)[2]), "+f"((c)[3])                 \
        : "r"((a)[0]), "r"((a)[1]), "r"((a)[2]), "r"((a)[3]),                    \
          "r"((b)[0]), "r"((b)[1]))

// tf32 mma m16n8k8 (small GEMMs)
#define MMA_TF32(c, a, b)                                                        \
    asm volatile(                                                                \
        "mma.sync.aligned.m16n8k8.row.col.f32.tf32.tf32.f32 "                    \
        "{%0,%1,%2,%3},{%4,%5,%6,%7},{%8,%9},{%0,%1,%2,%3};\n"                   \
        : "+f"((c)[0]), "+f"((c)[1]), "+f"((c)[2]), "+f"((c)[3])                 \
        : "r"((a)[0]), "r"((a)[1]), "r"((a)[2]), "r"((a)[3]),                    \
          "r"((b)[0]), "r"((b)[1]))

// ---------------- k_prep : fused Wc transpose | h = state@Wh+bh --------------
#define PREP_TR_BLKS 1024            // 32x32 tiles of Wc
#define PREP_TOTAL (PREP_TR_BLKS + BB)

__global__ void k_prep(const float* __restrict__ Wc,
                       const float* __restrict__ state, const float* __restrict__ Wh,
                       const float* __restrict__ bh) {
    __shared__ float sbuf[32 * 33];
    const int bx = blockIdx.x, tid = threadIdx.x;

    if (bx < PREP_TR_BLKS) {
        int j0 = (bx & 31) * 32, k0 = (bx >> 5) * 32;
        int lx = tid & 31, ly = tid >> 5;   // lx: 0..31, ly: 0..7
        float (*t)[33] = reinterpret_cast<float(*)[33]>(sbuf);
#pragma unroll
        for (int i = 0; i < 4; i++) {
            int kk = ly + i * 8;
            t[kk][lx] = Wc[(size_t)(k0 + kk) * UU + j0 + lx];
        }
        __syncthreads();
#pragma unroll
        for (int i = 0; i < 4; i++) {
            int jj = ly + i * 8;
            g_WcTH[(size_t)(j0 + jj) * ENCD + k0 + lx] = __float2half_rn(t[lx][jj]);
        }
    } else {
        int b = bx - PREP_TR_BLKS;
        float* ss = sbuf;
        for (int i = tid; i < UU; i += 256) ss[i] = state[b * UU + i];
        __syncthreads();
        float acc[4] = {0.f, 0.f, 0.f, 0.f};
#pragma unroll 4
        for (int k = 0; k < UU; k++) {
            float sv = ss[k];
            const float* wr = Wh + (size_t)k * UU + tid;
            acc[0] += sv * wr[0];
            acc[1] += sv * wr[256];
            acc[2] += sv * wr[512];
            acc[3] += sv * wr[768];
        }
#pragma unroll
        for (int jj = 0; jj < 4; jj++) {
            int j = tid + jj * 256;
            g_h[b * UU + j] = acc[jj] + bh[j];
        }
    }
}

// ---------------- k_score : fp16 mma, BK=64, 2-stage pipeline ----------------
// prologue converts own 128-row enc block fp32->fp16 into g_encH, then
// 8 j-tiles x 16 k-chunks = 128 pipeline iterations
#define SKW 36                   // smem row stride in words (32 data + 4 pad)
#define NST 2
#define STGW (128 * SKW)
#define STGB (STGW * 4)
#define SC_SMEM (2 * NST * STGB + 3 * 128 * 4)

__global__ __launch_bounds__(256, 2) void k_score(const float* __restrict__ enc,
                                                  const float* __restrict__ bc,
                                                  const float* __restrict__ Ws) {
    extern __shared__ char dsm[];
    uint32_t* sAp = reinterpret_cast<uint32_t*>(dsm);
    uint32_t* sBp = sAp + NST * STGW;
    float* shb = reinterpret_cast<float*>(sBp + NST * STGW);
    float* sws = shb + 128;
    float* srow = sws + 128;

    const int tid = threadIdx.x, wid = tid >> 5, lane = tid & 31;
    const int wm = wid & 1, wn = wid >> 1;
    const int g = lane >> 2, tg = lane & 3;
    const int R0 = blockIdx.x * 128;
    const int bidx = blockIdx.x >> 4;      // 2048 rows per batch element

    if (tid < 128) srow[tid] = 0.f;

    // ---- prologue: convert own block fp32 -> fp16 into g_encH ----
    {
        const float* aF = enc + (size_t)R0 * ENCD;
        __half* aHw = g_encH + (size_t)R0 * ENCD;
#pragma unroll 4
        for (int i = tid; i < 128 * ENCD / 8; i += 256) {
            size_t off = (size_t)i * 8;
            float4 v0 = *reinterpret_cast<const float4*>(aF + off);
            float4 v1 = *reinterpret_cast<const float4*>(aF + off + 4);
            __half2 h[4];
            h[0] = __floats2half2_rn(v0.x, v0.y);
            h[1] = __floats2half2_rn(v0.z, v0.w);
            h[2] = __floats2half2_rn(v1.x, v1.y);
            h[3] = __floats2half2_rn(v1.z, v1.w);
            *reinterpret_cast<uint4*>(aHw + off) = *reinterpret_cast<uint4*>(h);
        }
        __threadfence();
        __syncthreads();
    }

    const uint32_t sA0 = smem_u32(sAp);
    const uint32_t sB0 = smem_u32(sBp);
    const __half* aBase = g_encH + (size_t)R0 * ENCD;

    // ldmatrix per-lane byte offsets within a stage (ks adds ks*32 bytes)
    uint32_t aOff[4], bOff[2];
#pragma unroll
    for (int mt = 0; mt < 4; mt++) {
        int row = wm * 64 + mt * 16 + ((lane >> 3) & 1) * 8 + (lane & 7);
        aOff[mt] = (row * SKW + ((lane >> 4) << 2)) * 4;
    }
#pragma unroll
    for (int np = 0; np < 2; np++) {
        int row = wn * 32 + np * 16 + ((lane >> 4) & 1) * 8 + (lane & 7);
        bOff[np] = (row * SKW + (((lane >> 3) & 1) << 2)) * 4;
    }

    auto load_it = [&](int it) {
        int kc = it & 15, jt = it >> 4, s = it & 1;
        const __half* aSrc = aBase + kc * 64;
        const __half* bSrc = g_WcTH + (size_t)(jt * 128) * ENCD + kc * 64;
        uint32_t aDst = sA0 + s * STGB;
        uint32_t bDst = sB0 + s * STGB;
#pragma unroll
        for (int i = 0; i < 4; i++) {
            int idx = tid + i * 256;        // 0..1023
            int row = idx >> 3, seg = idx & 7;
            cp16(aDst + (row * SKW + seg * 4) * 4, aSrc + (size_t)row * ENCD + seg * 8);
            cp16(bDst + (row * SKW + seg * 4) * 4, bSrc + (size_t)row * ENCD + seg * 8);
        }
    };

    float c[4][4][4];
#pragma unroll
    for (int a = 0; a < 4; a++)
#pragma unroll
        for (int b2 = 0; b2 < 4; b2++)
#pragma unroll
            for (int d = 0; d < 4; d++) c[a][b2][d] = 0.f;
    float rowacc[4][2] = {{0.f, 0.f}, {0.f, 0.f}, {0.f, 0.f}, {0.f, 0.f}};

    load_it(0); CP_COMMIT();

    const int TOT = 128;
    for (int it = 0; it < TOT; it++) {
        const int kc = it & 15, jt = it >> 4, s = it & 1;
        CP_WAIT0();
        __syncthreads();

        if (kc == 0 && tid < 128) {
            int j = jt * 128 + tid;
            shb[tid] = g_h[bidx * UU + j] + bc[j];
            sws[tid] = Ws[j];
        }

        if (it + 1 < TOT) load_it(it + 1);
        CP_COMMIT();

        const uint32_t aB = sA0 + s * STGB;
        const uint32_t bB = sB0 + s * STGB;
#pragma unroll
        for (int ks = 0; ks < 4; ks++) {
            uint32_t bf[4][2];
#pragma unroll
            for (int np = 0; np < 2; np++)
                LDSM4(bf[2 * np][0], bf[2 * np][1], bf[2 * np + 1][0], bf[2 * np + 1][1],
                      bB + bOff[np] + ks * 32);
#pragma unroll
            for (int mt = 0; mt < 4; mt++) {
                uint32_t af[4];
                LDSM4(af[0], af[1], af[2], af[3], aB + aOff[mt] + ks * 32);
#pragma unroll
                for (int nt = 0; nt < 4; nt++) MMA_F16(c[mt][nt], af, bf[nt]);
            }
        }

        if (kc == 15) {
#pragma unroll
            for (int mt = 0; mt < 4; mt++) {
                float rs0 = 0.f, rs1 = 0.f;
#pragma unroll
                for (int nt = 0; nt < 4; nt++) {
                    int nl = wn * 32 + nt * 8 + tg * 2;
#pragma unroll
                    for (int cc = 0; cc < 2; cc++) {
                        float hb = shb[nl + cc], ws = sws[nl + cc];
                        rs0 += htanh(c[mt][nt][cc] + hb) * ws;
                        rs1 += htanh(c[mt][nt][2 + cc] + hb) * ws;
                    }
                }
                rs0 += __shfl_xor_sync(0xffffffffu, rs0, 1);
                rs0 += __shfl_xor_sync(0xffffffffu, rs0, 2);
                rs1 += __shfl_xor_sync(0xffffffffu, rs1, 1);
                rs1 += __shfl_xor_sync(0xffffffffu, rs1, 2);
                rowacc[mt][0] += rs0;
                rowacc[mt][1] += rs1;
#pragma unroll
                for (int nt = 0; nt < 4; nt++)
#pragma unroll
                    for (int d = 0; d < 4; d++) c[mt][nt][d] = 0.f;
            }
        }
    }

#pragma unroll
    for (int mt = 0; mt < 4; mt++) {
        if (tg == 0) {
            atomicAdd(&srow[wm * 64 + mt * 16 + g], rowacc[mt][0]);
            atomicAdd(&srow[wm * 64 + mt * 16 + 8 + g], rowacc[mt][1]);
        }
    }
    __syncthreads();
    if (tid < 128) g_s[R0 + tid] = srow[tid];
}

// ---------------- k_softmax ---------------------------------------------------
__global__ void k_softmax(const float* __restrict__ bs) {
    __shared__ float sv[SRC];
    __shared__ float red[256];
    int b = blockIdx.x, tid = threadIdx.x;
    float bsv = bs[0];
    float lmax = -1e30f;
    for (int t = tid; t < SRC; t += 256) {
        float s = bsv + g_s[b * SRC + t];
        sv[t] = s;
        lmax = fmaxf(lmax, s);
    }
    red[tid] = lmax;
    __syncthreads();
    for (int off = 128; off; off >>= 1) {
        if (tid < off) red[tid] = fmaxf(red[tid], red[tid + off]);
        __syncthreads();
    }
    float m = red[0];
    __syncthreads();
    float lsum = 0.f;
    for (int t = tid; t < SRC; t += 256) {
        float e = expf(sv[t] - m);
        sv[t] = e;
        lsum += e;
    }
    red[tid] = lsum;
    __syncthreads();
    for (int off = 128; off; off >>= 1) {
        if (tid < off) red[tid] += red[tid + off];
        __syncthreads();
    }
    float inv = 1.f / red[0];
    for (int t = tid; t < SRC; t += 256) g_w[b * SRC + t] = sv[t] * inv;
}

// ---------------- k_ctx : segmented weighted sum, half2 loads ----------------
// grid: (ENCD/512, BB, 8), each thread covers 2 columns
__global__ void k_ctx() {
    __shared__ float sw[256];
    int b = blockIdx.y, seg = blockIdx.z;
    int k2 = blockIdx.x * 256 + threadIdx.x;     // half2 column index
    int t0 = seg * 256;
    sw[threadIdx.x] = g_w[b * SRC + t0 + threadIdx.x];
    __syncthreads();
    const __half2* ep = reinterpret_cast<const __half2*>(
                            g_encH + ((size_t)b * SRC + t0) * ENCD) + k2;
    float ax0 = 0.f, ay0 = 0.f, ax1 = 0.f, ay1 = 0.f;
    float ax2 = 0.f, ay2 = 0.f, ax3 = 0.f, ay3 = 0.f;
#pragma unroll 2
    for (int t = 0; t < 256; t += 4) {
        float2 v0 = __half22float2(ep[(size_t)t * (ENCD / 2)]);
        float2 v1 = __half22float2(ep[(size_t)(t + 1) * (ENCD / 2)]);
        float2 v2 = __half22float2(ep[(size_t)(t + 2) * (ENCD / 2)]);
        float2 v3 = __half22float2(ep[(size_t)(t + 3) * (ENCD / 2)]);
        float w0 = sw[t], w1 = sw[t + 1], w2 = sw[t + 2], w3 = sw[t + 3];
        ax0 += w0 * v0.x; ay0 += w0 * v0.y;
        ax1 += w1 * v1.x; ay1 += w1 * v1.y;
        ax2 += w2 * v2.x; ay2 += w2 * v2.y;
        ax3 += w3 * v3.x; ay3 += w3 * v3.y;
    }
    g_ctxp[seg][b][2 * k2] = (ax0 + ax1) + (ax2 + ax3);
    g_ctxp[seg][b][2 * k2 + 1] = (ay0 + ay1) + (ay2 + ay3);
}

// ---------------- k_xin : xin = concat(sum(ctx partials), emb[x]) ------------
__global__ void k_xin(const int* __restrict__ x, const float* __restrict__ emb) {
    int b = blockIdx.x;
    int xi = x[b];
    for (int i = threadIdx.x; i < IN0; i += 256) {
        float v;
        if (i < ENCD) {
            v = 0.f;
#pragma unroll
            for (int seg = 0; seg < 8; seg++) v += g_ctxp[seg][b][i];
        } else {
            v = emb[(size_t)xi * EE + (i - ENCD)];
        }
        g_xin[b * IN0 + i] = v;
    }
}

// ---------------- legacy tf32 GEMM body: C(64xN) = A(64xKloop)@B [+bias] ----
template <int EPI>
__device__ __forceinline__ void gemm_body(const float* __restrict__ A,
                                          const float* __restrict__ B,
                                          const float* __restrict__ bias,
                                          float* __restrict__ C,
                                          int lda, int Kloop, int N, int col0) {
    __shared__ __align__(16) unsigned sA[64 * 36];
    __shared__ __align__(16) unsigned sB[32 * 132];
    const int tid = threadIdx.x;
    const int wid = tid >> 5, lane = tid & 31;
    const int wm = wid & 1, wn = wid >> 1;
    const int g = lane >> 2, tg = lane & 3;

    float c[2][4][4];
#pragma unroll
    for (int a = 0; a < 2; a++)
#pragma unroll
        for (int b2 = 0; b2 < 4; b2++)
#pragma unroll
            for (int d = 0; d < 4; d++) c[a][b2][d] = 0.f;

    for (int k0 = 0; k0 < Kloop; k0 += 32) {
#pragma unroll
        for (int i = 0; i < 2; i++) {
            int idx = tid + i * 256;
            int row = idx >> 3, c4 = idx & 7;
            float4 v = *reinterpret_cast<const float4*>(A + (size_t)row * lda + k0 + c4 * 4);
            *reinterpret_cast<uint4*>(&sA[row * 36 + c4 * 4]) = cvt4(v);
        }
#pragma unroll
        for (int i = 0; i < 4; i++) {
            int idx = tid + i * 256;
            int rb = idx >> 5, c4 = idx & 31;
            float4 v = *reinterpret_cast<const float4*>(B + (size_t)(k0 + rb) * N + col0 + c4 * 4);
            *reinterpret_cast<uint4*>(&sB[rb * 132 + c4 * 4]) = cvt4(v);
        }
        __syncthreads();
#pragma unroll
        for (int ks = 0; ks < 4; ks++) {
            const int kb = ks * 8;
            unsigned af[2][4], bf[4][2];
#pragma unroll
            for (int mt = 0; mt < 2; mt++) {
                int r = wm * 32 + mt * 16 + g;
                af[mt][0] = sA[r * 36 + kb + tg];
                af[mt][1] = sA[(r + 8) * 36 + kb + tg];
                af[mt][2] = sA[r * 36 + kb + tg + 4];
                af[mt][3] = sA[(r + 8) * 36 + kb + tg + 4];
            }
#pragma unroll
            for (int nt = 0; nt < 4; nt++) {
                int col = wn * 32 + nt * 8 + g;
                bf[nt][0] = sB[(kb + tg) * 132 + col];
                bf[nt][1] = sB[(kb + tg + 4) * 132 + col];
            }
#pragma unroll
            for (int mt = 0; mt < 2; mt++)
#pragma unroll
                for (int nt = 0; nt < 4; nt++) MMA_TF32(c[mt][nt], af[mt], bf[nt]);
        }
        __syncthreads();
    }
#pragma unroll
    for (int mt = 0; mt < 2; mt++)
#pragma unroll
        for (int nt = 0; nt < 4; nt++) {
            int r = wm * 32 + mt * 16 + g;
            int col = col0 + wn * 32 + nt * 8 + tg * 2;
            float add0 = 0.f, add1 = 0.f;
            if (EPI == 1) { add0 = bias[col]; add1 = bias[col + 1]; }
            C[(size_t)r * N + col] = c[mt][nt][0] + add0;
            C[(size_t)r * N + col + 1] = c[mt][nt][1] + add1;
            C[(size_t)(r + 8) * N + col] = c[mt][nt][2] + add0;
            C[(size_t)(r + 8) * N + col + 1] = c[mt][nt][3] + add1;
        }
}

template <int EPI>
__global__ __launch_bounds__(256, 2) void k_gemm(const float* __restrict__ A,
                                                 const float* __restrict__ B,
                                                 const float* __restrict__ bias,
                                                 float* __restrict__ C, int K, int N) {
    gemm_body<EPI>(A, B, bias, C, K, K, N, blockIdx.x * 128);
}

// split-K paired GEMM: grid (N/128, 2 pairs, 4 splits)
__global__ __launch_bounds__(256, 2) void k_gemm_splitk(
    const float* A0, const float* A1, const float* B0, const float* B1,
    float* Cp, int K, int N) {
    const int pair = blockIdx.y, z = blockIdx.z;
    const float* A = pair ? A1 : A0;
    const float* B = pair ? B1 : B0;
    const int Ks = K / 4;
    float* C = Cp + ((size_t)z * 2 + pair) * XSEG;
    gemm_body<0>(A + z * Ks, B + (size_t)z * Ks * N, nullptr, C,
                 K, Ks, N, blockIdx.x * 128);
}

// ---------------- k_gru_pair : sums 4 split-K partials + pointwise GRU ------
// optional y0/y1: also write into concat buffer halves
__global__ void k_gru_pair(const float* xgp, const float* b0v, const float* b1v,
                           float* o0, float* o1, float* y0, float* y1) {
    const int pair = blockIdx.y;
    const float* xg = xgp + (size_t)pair * XSEG;
    const float* bvec = pair ? b1v : b0v;
    float* hout = pair ? o1 : o0;
    float* yout = pair ? y1 : y0;
    int b = blockIdx.x;
    const size_t ZS = 2 * (size_t)XSEG;
    for (int u = threadIdx.x; u < UU; u += 256) {
        size_t iz = (size_t)b * 3 * UU + u;
        size_t ir = iz + UU, ih = iz + 2 * UU;
        float xz = xg[iz] + xg[iz + ZS] + xg[iz + 2 * ZS] + xg[iz + 3 * ZS]
                 + bvec[u] + bvec[3 * UU + u];
        float xr = xg[ir] + xg[ir + ZS] + xg[ir + 2 * ZS] + xg[ir + 3 * ZS]
                 + bvec[UU + u] + bvec[3 * UU + UU + u];
        float xh = xg[ih] + xg[ih + ZS] + xg[ih + 2 * ZS] + xg[ih + 3 * ZS]
                 + bvec[2 * UU + u];
        float b1h = bvec[3 * UU + 2 * UU + u];
        float z = 1.f / (1.f + expf(-xz));
        float r = 1.f / (1.f + expf(-xr));
        float hc = tanhf(xh + r * b1h);
        float h = (1.f - z) * hc;
        hout[b * UU + u] = h;
        if (yout) yout[b * 2 * UU + u] = h;
    }
}

// ---------------- host launcher ----------------------------------------------
extern "C" void kernel_launch(void* const* d_in, const int* in_sizes, int n_in,
                              void* d_out, int out_size) {
    (void)in_sizes; (void)n_in; (void)out_size;
    const int* x = (const int*)d_in[0];
    const float* state = (const float*)d_in[1];
    const float* enc = (const float*)d_in[2];
    const float* Wh = (const float*)d_in[3];
    const float* bh = (const float*)d_in[4];
    const float* Wc = (const float*)d_in[5];
    const float* bc = (const float*)d_in[6];
    const float* Ws = (const float*)d_in[7];
    const float* bs = (const float*)d_in[8];
    const float* emb = (const float*)d_in[9];
    const float* fw0_k = (const float*)d_in[10];
    const float* fw0_b = (const float*)d_in[12];
    const float* fw1_k = (const float*)d_in[13];
    const float* fw1_b = (const float*)d_in[15];
    const float* bw0_k = (const float*)d_in[16];
    const float* bw0_b = (const float*)d_in[18];
    const float* bw1_k = (const float*)d_in[19];
    const float* bw1_b = (const float*)d_in[21];
    const float* fcW = (const float*)d_in[22];
    const float* fcb = (const float*)d_in[23];

    float* out = (float*)d_out;
    float* h0f = out + (size_t)BB * VV;
    float* h1f = h0f + BB * UU;
    float* h0b = h1f + BB * UU;
    float* h1b = h0b + BB * UU;

    float *p_xin, *p_xgp, *p_y;
    cudaGetSymbolAddress((void**)&p_xin, g_xin);
    cudaGetSymbolAddress((void**)&p_xgp, g_xgp);
    cudaGetSymbolAddress((void**)&p_y, g_y);

    cudaFuncSetAttribute(k_score, cudaFuncAttributeMaxDynamicSharedMemorySize, SC_SMEM);

    // attention
    k_prep<<<PREP_TOTAL, 256>>>(Wc, state, Wh, bh);
    k_score<<<MROWS / 128, 256, SC_SMEM>>>(enc, bc, Ws);
    k_softmax<<<BB, 256>>>(bs);
    k_ctx<<<dim3(ENCD / 512, BB, 8), 256>>>();
    k_xin<<<BB, 256>>>(x, emb);

    // GRU stacks (zero hidden state => rk unused); fw/bw paired, split-K x4
    k_gemm_splitk<<<dim3(3 * UU / 128, 2, 4), 256>>>(p_xin, p_xin, fw0_k, bw0_k,
                                                     p_xgp, IN0, 3 * UU);
    k_gru_pair<<<dim3(BB, 2), 256>>>(p_xgp, fw0_b, bw0_b, h0f, h0b, nullptr, nullptr);
    k_gemm_splitk<<<dim3(3 * UU / 128, 2, 4), 256>>>(h0f, h0b, fw1_k, bw1_k,
                                                     p_xgp, UU, 3 * UU);
    k_gru_pair<<<dim3(BB, 2), 256>>>(p_xgp, fw1_b, bw1_b, h1f, h1b,
                                     p_y, p_y + UU);

    // output projection
    k_gemm<1><<<dim3(VV / 128, 1), 256>>>(p_y, fcW, fcb, out, 2 * UU, VV);
}